// round 8
// baseline (speedup 1.0000x reference)
#include <cuda_runtime.h>
#include <cuda_bf16.h>
#include <math.h>
#include <stdint.h>

#define EMBED 768
#define HEADS 12
#define HD    64
#define MLPD  3072
#define BATCH 4
#define SEQ   1024
#define ROWS  (BATCH*SEQ)
#define QKVW  (3*EMBED)
#define BH    (BATCH*HEADS)

typedef __nv_bfloat16 bf16;

// ------------------------- scratch ------------------------------------------
__device__ float  g_h32 [ROWS*EMBED];
__device__ int8_t g_hq1[ROWS*EMBED],  g_hq2[ROWS*EMBED];
__device__ float  g_sa_h[ROWS];
__device__ int8_t g_wqkv8a[QKVW*EMBED], g_wqkv8b[QKVW*EMBED];
__device__ float  g_sb_qkv[QKVW];
__device__ bf16   g_woutT_hi[EMBED*EMBED], g_woutT_lo[EMBED*EMBED];
__device__ int8_t g_w18a[MLPD*EMBED], g_w18b[MLPD*EMBED];
__device__ float  g_sb_w1[MLPD];
__device__ int8_t g_w28a[EMBED*MLPD], g_w28b[EMBED*MLPD];
__device__ float  g_sb_w2[EMBED];
__device__ bf16   g_qkv_hi[ROWS*QKVW], g_qkv_lo[ROWS*QKVW];
__device__ bf16   g_attn_hi[ROWS*EMBED], g_attn_lo[ROWS*EMBED];
__device__ float  g_x2[ROWS*EMBED];
__device__ int8_t g_h2q1[ROWS*EMBED], g_h2q2[ROWS*EMBED];
__device__ float  g_sa_h2[ROWS];
__device__ bf16   g_mid_hi[ROWS*MLPD], g_mid_lo[ROWS*MLPD];
__device__ int8_t g_midq1[ROWS*MLPD], g_midq2[ROWS*MLPD];
__device__ float  g_sa_mid[ROWS];
__device__ float  g_cm_qkv[QKVW], g_cm_w1[MLPD], g_cm_w2[EMBED];

// ------------------------- helpers ------------------------------------------
__device__ __forceinline__ uint32_t smem_u32(const void* p){
    uint32_t a;
    asm("{ .reg .u64 t; cvta.to.shared.u64 t, %1; cvt.u32.u64 %0, t; }" : "=r"(a) : "l"(p));
    return a;
}
__device__ __forceinline__ void split_bf(float v, bf16& h, bf16& l){
    h = __float2bfloat16(v);
    l = __float2bfloat16(v - __bfloat162float(h));
}
__device__ __forceinline__ void cp16(uint32_t dst, const void* src){
    asm volatile("cp.async.cg.shared.global [%0], [%1], 16;" :: "r"(dst), "l"(src));
}
__device__ __forceinline__ void ldsm4(uint32_t* r, uint32_t a){
    asm volatile("ldmatrix.sync.aligned.m8n8.x4.shared.b16 {%0,%1,%2,%3}, [%4];"
        : "=r"(r[0]),"=r"(r[1]),"=r"(r[2]),"=r"(r[3]) : "r"(a));
}
__device__ __forceinline__ void ldsm4t(uint32_t* r, uint32_t a){
    asm volatile("ldmatrix.sync.aligned.m8n8.x4.trans.shared.b16 {%0,%1,%2,%3}, [%4];"
        : "=r"(r[0]),"=r"(r[1]),"=r"(r[2]),"=r"(r[3]) : "r"(a));
}
__device__ __forceinline__ void ldsm2(uint32_t* r, uint32_t a){
    asm volatile("ldmatrix.sync.aligned.m8n8.x2.shared.b16 {%0,%1}, [%2];"
        : "=r"(r[0]),"=r"(r[1]) : "r"(a));
}
__device__ __forceinline__ void mma16816(float* c, const uint32_t* a, const uint32_t* b){
    asm volatile("mma.sync.aligned.m16n8k16.row.col.f32.bf16.bf16.f32 "
        "{%0,%1,%2,%3}, {%4,%5,%6,%7}, {%8,%9}, {%0,%1,%2,%3};"
        : "+f"(c[0]),"+f"(c[1]),"+f"(c[2]),"+f"(c[3])
        : "r"(a[0]),"r"(a[1]),"r"(a[2]),"r"(a[3]), "r"(b[0]),"r"(b[1]));
}
__device__ __forceinline__ void imma16832(int* c, const uint32_t* a, const uint32_t* b){
    asm volatile("mma.sync.aligned.m16n8k32.row.col.s32.s8.s8.s32 "
        "{%0,%1,%2,%3}, {%4,%5,%6,%7}, {%8,%9}, {%0,%1,%2,%3};"
        : "+r"(c[0]),"+r"(c[1]),"+r"(c[2]),"+r"(c[3])
        : "r"(a[0]),"r"(a[1]),"r"(a[2]),"r"(a[3]), "r"(b[0]),"r"(b[1]));
}
__device__ __forceinline__ uint32_t pack_bf2(bf16 a, bf16 b){
    return (uint32_t)__bfloat16_as_ushort(a) | ((uint32_t)__bfloat16_as_ushort(b) << 16);
}
__device__ __forceinline__ void pack_split(float x, float y, uint32_t& hp, uint32_t& lp){
    bf16 hx, lx, hy, ly;
    split_bf(x, hx, lx); split_bf(y, hy, ly);
    hp = pack_bf2(hx, hy);
    lp = pack_bf2(lx, ly);
}
__device__ __forceinline__ void quant2(float v, float inv_s, float s, int8_t& q1, int8_t& q2){
    int a = __float2int_rn(v * inv_s);
    a = max(-127, min(127, a));
    float r = v - s * (float)a;
    int c = __float2int_rn(r * inv_s * 128.f);
    c = max(-127, min(127, c));
    q1 = (int8_t)a; q2 = (int8_t)c;
}

// ------------------------- weight prep --------------------------------------
__global__ void zcm(float* a, int n){
    int i = blockIdx.x*256 + threadIdx.x;
    if (i < n) a[i] = 0.f;
}
__global__ void wcolmax(const float* __restrict__ W, float* __restrict__ cm, int K, int N){
    const int n = blockIdx.x*256 + threadIdx.x;
    const int k0 = blockIdx.y*256;
    float m = 0.f;
    for (int k = k0; k < k0 + 256 && k < K; k++)
        m = fmaxf(m, fabsf(W[(size_t)k*N + n]));
    atomicMax((unsigned int*)&cm[n], __float_as_uint(m));
}
__global__ void tconv8(const float* __restrict__ W, const float* __restrict__ cm,
                       int8_t* __restrict__ T1, int8_t* __restrict__ T2,
                       float* __restrict__ sb, int K, int N)
{
    __shared__ float s[32][33];
    const int n0 = blockIdx.x * 32, k0 = blockIdx.y * 32;
    const int tx = threadIdx.x, ty = threadIdx.y;
    #pragma unroll
    for (int i = 0; i < 4; i++)
        s[ty + i*8][tx] = W[(size_t)(k0 + ty + i*8) * N + n0 + tx];
    __syncthreads();
    #pragma unroll
    for (int i = 0; i < 4; i++) {
        const int n = ty + i*8;
        const float cmv = fmaxf(cm[n0+n], 1e-30f);
        const float sc = cmv / 127.f, inv = 127.f / cmv;
        int8_t q1, q2;
        quant2(s[tx][n], inv, sc, q1, q2);
        const size_t o = (size_t)(n0 + n) * K + k0 + tx;
        T1[o] = q1; T2[o] = q2;
        if (k0 == 0 && tx == 0) sb[n0+n] = sc;
    }
}
// bf16 hi/lo transpose (w_out only)
__global__ void tconv(const float* __restrict__ W, bf16* __restrict__ Thi, bf16* __restrict__ Tlo,
                      int K, int N)
{
    __shared__ float s[32][33];
    const int n0 = blockIdx.x * 32, k0 = blockIdx.y * 32;
    const int tx = threadIdx.x, ty = threadIdx.y;
    #pragma unroll
    for (int i = 0; i < 4; i++)
        s[ty + i*8][tx] = W[(size_t)(k0 + ty + i*8) * N + n0 + tx];
    __syncthreads();
    #pragma unroll
    for (int i = 0; i < 4; i++) {
        const int n = ty + i*8;
        bf16 h, l; split_bf(s[tx][n], h, l);
        const size_t o = (size_t)(n0 + n) * K + k0 + tx;
        Thi[o] = h; Tlo[o] = l;
    }
}

// ------------------------- LayerNorm -> int8 planes -------------------------
__global__ __launch_bounds__(256) void ln8(const float* __restrict__ x,
                                           const float* __restrict__ g,
                                           const float* __restrict__ b,
                                           float* __restrict__ out32,
                                           int8_t* __restrict__ q1p,
                                           int8_t* __restrict__ q2p,
                                           float* __restrict__ sa)
{
    const int row = blockIdx.x;
    const int t = threadIdx.x;
    const float* xr = x + (size_t)row * EMBED;
    float v0 = xr[t], v1 = xr[t+256], v2 = xr[t+512];
    float s = v0+v1+v2, sq = v0*v0+v1*v1+v2*v2;
    #pragma unroll
    for (int off = 16; off; off >>= 1) {
        s  += __shfl_xor_sync(0xffffffffu, s,  off);
        sq += __shfl_xor_sync(0xffffffffu, sq, off);
    }
    __shared__ float red[24];
    const int w = t >> 5;
    if ((t & 31) == 0) { red[w] = s; red[8+w] = sq; }
    __syncthreads();
    float tot = 0.f, totq = 0.f;
    #pragma unroll
    for (int i = 0; i < 8; i++) { tot += red[i]; totq += red[8+i]; }
    const float mu = tot * (1.f/768.f);
    const float var = totq * (1.f/768.f) - mu*mu;
    const float rstd = rsqrtf(fmaxf(var, 0.f) + 1e-5f);
    const size_t o = (size_t)row * EMBED;
    float y[3];
    #pragma unroll
    for (int i = 0; i < 3; i++) {
        const int c = t + i*256;
        const float v = (i==0?v0:(i==1?v1:v2));
        y[i] = (v - mu) * rstd * g[c] + b[c];
        if (out32) out32[o + c] = y[i];
    }
    float am = fmaxf(fabsf(y[0]), fmaxf(fabsf(y[1]), fabsf(y[2])));
    #pragma unroll
    for (int off = 16; off; off >>= 1) am = fmaxf(am, __shfl_xor_sync(0xffffffffu, am, off));
    if ((t & 31) == 0) red[16+w] = am;
    __syncthreads();
    float bm = red[16];
    #pragma unroll
    for (int i = 1; i < 8; i++) bm = fmaxf(bm, red[16+i]);
    bm = fmaxf(bm, 1e-30f);
    const float sc = bm / 127.f, inv = 127.f / bm;
    #pragma unroll
    for (int i = 0; i < 3; i++) {
        int8_t q1, q2;
        quant2(y[i], inv, sc, q1, q2);
        q1p[o + t + i*256] = q1; q2p[o + t + i*256] = q2;
    }
    if (t == 0) sa[row] = sc;
}

// ------------------------- mid (bf16 hi/lo) -> int8 planes ------------------
__global__ __launch_bounds__(256) void quant8(const bf16* __restrict__ hi, const bf16* __restrict__ lo,
                                              int8_t* __restrict__ q1p, int8_t* __restrict__ q2p,
                                              float* __restrict__ sa)
{
    const int row = blockIdx.x;
    const int t = threadIdx.x;
    const size_t base = (size_t)row * MLPD;
    float v[12];
    float am = 0.f;
    #pragma unroll
    for (int i = 0; i < 12; i++) {
        const int c = t + i*256;
        v[i] = __bfloat162float(hi[base+c]) + __bfloat162float(lo[base+c]);
        am = fmaxf(am, fabsf(v[i]));
    }
    #pragma unroll
    for (int off = 16; off; off >>= 1) am = fmaxf(am, __shfl_xor_sync(0xffffffffu, am, off));
    __shared__ float red[8];
    const int w = t >> 5;
    if ((t & 31) == 0) red[w] = am;
    __syncthreads();
    float bm = red[0];
    #pragma unroll
    for (int i = 1; i < 8; i++) bm = fmaxf(bm, red[i]);
    bm = fmaxf(bm, 1e-30f);
    const float sc = bm / 127.f, inv = 127.f / bm;
    #pragma unroll
    for (int i = 0; i < 12; i++) {
        int8_t q1, q2;
        quant2(v[i], inv, sc, q1, q2);
        q1p[base + t + i*256] = q1; q2p[base + t + i*256] = q2;
    }
    if (t == 0) sa[row] = sc;
}

// ------------------------- int8 dual-plane GEMM -----------------------------
// C[m][n] = sum_k A[m][k]B[n][k], A/B = s*(q1 + q2/128). Per k32: 3 IMMA
// (q1q1 -> d1; q1a*q2b + q2a*q1b -> d23), folded to fp32 each step.
// EPI 0: qkv (split bf16, cols<768 *0.125)  1: split(gelu(+bias))
// EPI 2: f32 +bias+add1
template<int EPI>
__global__ void __launch_bounds__(256, 2) gemm_i8(
    const int8_t* __restrict__ Aq1, const int8_t* __restrict__ Aq2, const float* __restrict__ sa, int lda,
    const int8_t* __restrict__ Bq1, const int8_t* __restrict__ Bq2, const float* __restrict__ sb, int ldb,
    float* __restrict__ C, bf16* __restrict__ Chi, bf16* __restrict__ Clo, int ldc,
    const float* __restrict__ bias, const float* __restrict__ add1,
    int K)
{
    constexpr int RS  = 80;
    constexpr int SP  = 128 * RS;     // 10240 per plane (128 rows x 64B + pad)
    constexpr int BUF = 4 * SP;       // A1 A2 B1 B2

    extern __shared__ char sm[];
    const uint32_t smb = smem_u32(sm);
    const int tid  = threadIdx.x;
    const int wid  = tid >> 5, lane = tid & 31;
    const int warp_m = wid & 1, warp_n = wid >> 1;
    const int rowBase = blockIdx.y * 128;
    const int colBase = blockIdx.x * 128;

    float acc[4][4][4];
    #pragma unroll
    for (int mt = 0; mt < 4; mt++)
        #pragma unroll
        for (int nt = 0; nt < 4; nt++)
            #pragma unroll
            for (int i = 0; i < 4; i++) acc[mt][nt][i] = 0.f;

    auto load_chunk = [&](int c) {
        const uint32_t st = smb + (c & 1)*BUF;
        const int k0 = c * 64;
        #pragma unroll
        for (int i = 0; i < 8; i++) {
            const int t = tid + i*256;
            const int pl = t >> 9, rem = t & 511, rr = rem >> 2, cg = rem & 3;
            const int8_t* base = (pl==0) ? Aq1 : (pl==1) ? Aq2 : (pl==2) ? Bq1 : Bq2;
            const int rb = (pl < 2) ? rowBase : colBase;
            const int ld = (pl < 2) ? lda : ldb;
            cp16(st + pl*SP + rr*RS + cg*16, base + (size_t)(rb + rr)*ld + k0 + cg*16);
        }
        asm volatile("cp.async.commit_group;");
    };

    load_chunk(0);
    const int NC = K / 64;
    for (int c = 0; c < NC; ++c) {
        asm volatile("cp.async.wait_group 0;" ::: "memory");
        __syncthreads();
        if (c + 1 < NC) load_chunk(c + 1);

        const uint32_t st = smb + (c & 1)*BUF;
        #pragma unroll
        for (int ks = 0; ks < 2; ks++) {
            uint32_t b1[4][2], b2[4][2];
            #pragma unroll
            for (int nt = 0; nt < 4; nt++) {
                const int row = warp_n*32 + nt*8 + (lane & 7);
                const uint32_t ad = st + 2*SP + row*RS + ks*32 + ((lane >> 3) & 1)*16;
                ldsm2(b1[nt], ad);
                ldsm2(b2[nt], ad + SP);
            }
            #pragma unroll
            for (int mt = 0; mt < 4; mt++) {
                const int row = warp_m*64 + mt*16 + (lane & 15);
                const uint32_t aad = st + row*RS + ks*32 + (lane >> 4)*16;
                uint32_t a1[4], a2[4];
                ldsm4(a1, aad);
                ldsm4(a2, aad + SP);
                #pragma unroll
                for (int nt = 0; nt < 4; nt++) {
                    int d1[4]  = {0,0,0,0};
                    int d23[4] = {0,0,0,0};
                    imma16832(d1,  a1, b1[nt]);
                    imma16832(d23, a1, b2[nt]);
                    imma16832(d23, a2, b1[nt]);
                    #pragma unroll
                    for (int i = 0; i < 4; i++)
                        acc[mt][nt][i] += (float)d1[i] + (float)d23[i] * 0.0078125f;
                }
            }
        }
    }

    #pragma unroll
    for (int mt = 0; mt < 4; mt++) {
        #pragma unroll
        for (int nt = 0; nt < 4; nt++) {
            const int gr0 = rowBase + warp_m*64 + mt*16 + (lane >> 2);
            const int gc  = colBase + warp_n*32 + nt*8 + (lane & 3)*2;
            const float sb0 = sb[gc], sb1 = sb[gc+1];
            #pragma unroll
            for (int half = 0; half < 2; half++) {
                const int gr = gr0 + half*8;
                const float sar = sa[gr];
                const size_t idx = (size_t)gr * ldc + gc;
                float v0 = acc[mt][nt][half*2 + 0] * sar * sb0;
                float v1 = acc[mt][nt][half*2 + 1] * sar * sb1;
                if (EPI == 2) {
                    v0 += bias[gc+0] + add1[idx+0];
                    v1 += bias[gc+1] + add1[idx+1];
                    *(float2*)(C + idx) = make_float2(v0, v1);
                } else {
                    if (EPI == 1) {
                        v0 += bias[gc+0];
                        v1 += bias[gc+1];
                        v0 = 0.5f * v0 * (1.f + erff(v0 * 0.70710678118654752f));
                        v1 = 0.5f * v1 * (1.f + erff(v1 * 0.70710678118654752f));
                    }
                    if (EPI == 0 && gc < EMBED) { v0 *= 0.125f; v1 *= 0.125f; }
                    uint32_t hp, lp;
                    pack_split(v0, v1, hp, lp);
                    *(uint32_t*)(Chi + idx) = hp;
                    *(uint32_t*)(Clo + idx) = lp;
                }
            }
        }
    }
}

// ------------------------- bf16 hi/lo GEMM (wout) ---------------------------
__global__ void __launch_bounds__(256, 2) gemm_wout(
    const bf16* __restrict__ Ahi, const bf16* __restrict__ Alo, int lda,
    const bf16* __restrict__ Bhi, const bf16* __restrict__ Blo, int ldb,
    float* __restrict__ C, int ldc,
    const float* __restrict__ bias, const float* __restrict__ add1, const float* __restrict__ add2,
    int K)
{
    constexpr int RS  = 80;
    constexpr int SA  = 128 * RS;
    constexpr int BUF = 4 * SA;

    extern __shared__ char sm[];
    const uint32_t smb = smem_u32(sm);
    const int tid  = threadIdx.x;
    const int wid  = tid >> 5, lane = tid & 31;
    const int warp_m = wid & 1, warp_n = wid >> 1;
    const int rowBase = blockIdx.y * 128;
    const int colBase = blockIdx.x * 128;

    float acc[4][4][4];
    #pragma unroll
    for (int mt = 0; mt < 4; mt++)
        #pragma unroll
        for (int nt = 0; nt < 4; nt++)
            #pragma unroll
            for (int i = 0; i < 4; i++) acc[mt][nt][i] = 0.f;

    auto load_chunk = [&](int c) {
        const uint32_t st = smb + (c & 1)*BUF;
        const int k0 = c * 32;
        #pragma unroll
        for (int i = 0; i < 4; i++) {
            const int t = tid + i*256;
            const int plane = t >> 9, rr = (t >> 2) & 127, cg = t & 3;
            const bf16* src = (plane ? Alo : Ahi) + (size_t)(rowBase + rr) * lda + k0 + cg*8;
            cp16(st + plane*SA + rr*RS + cg*16, src);
        }
        #pragma unroll
        for (int i = 0; i < 4; i++) {
            const int t = tid + i*256;
            const int plane = t >> 9, rr = (t >> 2) & 127, cg = t & 3;
            const bf16* src = (plane ? Blo : Bhi) + (size_t)(colBase + rr) * ldb + k0 + cg*8;
            cp16(st + 2*SA + plane*SA + rr*RS + cg*16, src);
        }
        asm volatile("cp.async.commit_group;");
    };

    load_chunk(0);
    const int NC = K / 32;
    for (int c = 0; c < NC; ++c) {
        asm volatile("cp.async.wait_group 0;" ::: "memory");
        __syncthreads();
        if (c + 1 < NC) load_chunk(c + 1);

        const uint32_t st = smb + (c & 1)*BUF;
        #pragma unroll
        for (int ks = 0; ks < 2; ks++) {
            uint32_t bh[4][2], bl[4][2];
            #pragma unroll
            for (int nt = 0; nt < 4; nt++) {
                const int row = warp_n*32 + nt*8 + (lane & 7);
                const uint32_t ad = st + 2*SA + row*RS + ks*32 + ((lane >> 3) & 1)*16;
                ldsm2(bh[nt], ad);
                ldsm2(bl[nt], ad + SA);
            }
            #pragma unroll
            for (int mt = 0; mt < 4; mt++) {
                const int row = warp_m*64 + mt*16 + (lane & 15);
                const uint32_t aad = st + row*RS + ks*32 + (lane >> 4)*16;
                uint32_t ah[4], al[4];
                ldsm4(ah, aad);
                ldsm4(al, aad + SA);
                #pragma unroll
                for (int nt = 0; nt < 4; nt++) {
                    mma16816(acc[mt][nt], ah, bh[nt]);
                    mma16816(acc[mt][nt], ah, bl[nt]);
                    mma16816(acc[mt][nt], al, bh[nt]);
                }
            }
        }
    }

    #pragma unroll
    for (int mt = 0; mt < 4; mt++) {
        #pragma unroll
        for (int nt = 0; nt < 4; nt++) {
            const int gr0 = rowBase + warp_m*64 + mt*16 + (lane >> 2);
            const int gc  = colBase + warp_n*32 + nt*8 + (lane & 3)*2;
            #pragma unroll
            for (int half = 0; half < 2; half++) {
                const int gr = gr0 + half*8;
                const size_t idx = (size_t)gr * ldc + gc;
                float v0 = acc[mt][nt][half*2 + 0] + bias[gc+0] + add1[idx+0] + add2[idx+0];
                float v1 = acc[mt][nt][half*2 + 1] + bias[gc+1] + add1[idx+1] + add2[idx+1];
                *(float2*)(C + idx) = make_float2(v0, v1);
            }
        }
    }
}

// ------------------------- fused flash attention ----------------------------
__global__ void __launch_bounds__(256) flash_attn(
    const bf16* __restrict__ qh_g, const bf16* __restrict__ ql_g,
    bf16* __restrict__ Ohi, bf16* __restrict__ Olo)
{
    extern __shared__ char sm[];
    const uint32_t smb = smem_u32(sm);
    const int tid = threadIdx.x, lane = tid & 31, wid = tid >> 5;
    const int qt = blockIdx.x;
    const int b  = blockIdx.y / HEADS, h = blockIdx.y % HEADS;
    const size_t gbase = (size_t)b * SEQ * QKVW;
    const int hoff = h * HD;

    #pragma unroll
    for (int i = 0; i < 8; i++) {
        const int t = tid + i*256;
        const int plane = t >> 10, rem = t & 1023, r = rem >> 3, cg = rem & 7;
        const bf16* src = (plane ? ql_g : qh_g) + gbase + (size_t)(qt*128 + r)*QKVW + hoff + cg*8;
        cp16(smb + plane*18432 + (uint32_t)(r*144 + cg*16), src);
    }
    auto load_kv = [&](int j) {
        const uint32_t dst = smb + 36864 + (j & 1)*36864;
        #pragma unroll
        for (int i = 0; i < 8; i++) {
            const int t = tid + i*256;
            const int q4 = t >> 9, rem = t & 511, r = rem >> 3, cg = rem & 7;
            const bf16* src = ((q4 & 1) ? ql_g : qh_g) + gbase
                + (size_t)(j*64 + r)*QKVW + EMBED + (q4 >> 1)*EMBED + hoff + cg*8;
            cp16(dst + (uint32_t)(q4*9216 + r*144 + cg*16), src);
        }
        asm volatile("cp.async.commit_group;");
    };
    load_kv(0);

    const int warprow = wid * 16;
    float m0 = -1e30f, m1 = -1e30f, l0 = 0.f, l1 = 0.f;
    float o[8][4];
    #pragma unroll
    for (int nt = 0; nt < 8; nt++)
        #pragma unroll
        for (int i = 0; i < 4; i++) o[nt][i] = 0.f;

    for (int j = 0; j < 16; j++) {
        asm volatile("cp.async.wait_group 0;" ::: "memory");
        __syncthreads();
        if (j < 15) load_kv(j + 1);
        const uint32_t st = smb + 36864 + (j & 1)*36864;

        float s[8][4];
        #pragma unroll
        for (int nt = 0; nt < 8; nt++)
            #pragma unroll
            for (int i = 0; i < 4; i++) s[nt][i] = 0.f;
        #pragma unroll
        for (int ks = 0; ks < 4; ks++) {
            uint32_t qh[4], ql[4];
            const uint32_t qa = smb + (uint32_t)((warprow + (lane & 15))*144 + ks*32 + (lane >> 4)*16);
            ldsm4(qh, qa);
            ldsm4(ql, qa + 18432);
            #pragma unroll
            for (int nt = 0; nt < 8; nt++) {
                uint32_t kh[2], kl[2];
                const uint32_t ka = st + (uint32_t)((nt*8 + (lane & 7))*144 + ks*32 + ((lane >> 3) & 1)*16);
                ldsm2(kh, ka);
                ldsm2(kl, ka + 9216);
                mma16816(s[nt], qh, kh);
                mma16816(s[nt], qh, kl);
                mma16816(s[nt], ql, kh);
            }
        }

        float mt0 = s[0][0], mt1 = s[0][2];
        #pragma unroll
        for (int nt = 0; nt < 8; nt++) {
            mt0 = fmaxf(mt0, fmaxf(s[nt][0], s[nt][1]));
            mt1 = fmaxf(mt1, fmaxf(s[nt][2], s[nt][3]));
        }
        mt0 = fmaxf(mt0, __shfl_xor_sync(0xffffffffu, mt0, 1));
        mt0 = fmaxf(mt0, __shfl_xor_sync(0xffffffffu, mt0, 2));
        mt1 = fmaxf(mt1, __shfl_xor_sync(0xffffffffu, mt1, 1));
        mt1 = fmaxf(mt1, __shfl_xor_sync(0xffffffffu, mt1, 2));
        const float mn0 = fmaxf(m0, mt0), mn1 = fmaxf(m1, mt1);
        const float a0 = __expf(m0 - mn0), a1 = __expf(m1 - mn1);
        float rs0 = 0.f, rs1 = 0.f;
        #pragma unroll
        for (int nt = 0; nt < 8; nt++) {
            s[nt][0] = __expf(s[nt][0] - mn0); rs0 += s[nt][0];
            s[nt][1] = __expf(s[nt][1] - mn0); rs0 += s[nt][1];
            s[nt][2] = __expf(s[nt][2] - mn1); rs1 += s[nt][2];
            s[nt][3] = __expf(s[nt][3] - mn1); rs1 += s[nt][3];
        }
        rs0 += __shfl_xor_sync(0xffffffffu, rs0, 1);
        rs0 += __shfl_xor_sync(0xffffffffu, rs0, 2);
        rs1 += __shfl_xor_sync(0xffffffffu, rs1, 1);
        rs1 += __shfl_xor_sync(0xffffffffu, rs1, 2);
        l0 = l0 * a0 + rs0;  l1 = l1 * a1 + rs1;
        m0 = mn0;  m1 = mn1;
        #pragma unroll
        for (int nt = 0; nt < 8; nt++) {
            o[nt][0] *= a0; o[nt][1] *= a0;
            o[nt][2] *= a1; o[nt][3] *= a1;
        }

        uint32_t ph[4][4], pl[4][4];
        #pragma unroll
        for (int ks = 0; ks < 4; ks++) {
            pack_split(s[2*ks][0],   s[2*ks][1],   ph[ks][0], pl[ks][0]);
            pack_split(s[2*ks][2],   s[2*ks][3],   ph[ks][1], pl[ks][1]);
            pack_split(s[2*ks+1][0], s[2*ks+1][1], ph[ks][2], pl[ks][2]);
            pack_split(s[2*ks+1][2], s[2*ks+1][3], ph[ks][3], pl[ks][3]);
        }

        #pragma unroll
        for (int ks = 0; ks < 4; ks++) {
            #pragma unroll
            for (int ntp = 0; ntp < 4; ntp++) {
                uint32_t vh[4], vl[4];
                const uint32_t va = st + 18432
                    + (uint32_t)((ks*16 + ((lane >> 3) & 1)*8 + (lane & 7))*144
                                 + ntp*32 + (lane >> 4)*16);
                ldsm4t(vh, va);
                ldsm4t(vl, va + 9216);
                mma16816(o[2*ntp],   ph[ks], &vh[0]);
                mma16816(o[2*ntp],   ph[ks], &vl[0]);
                mma16816(o[2*ntp],   pl[ks], &vh[0]);
                mma16816(o[2*ntp+1], ph[ks], &vh[2]);
                mma16816(o[2*ntp+1], ph[ks], &vl[2]);
                mma16816(o[2*ntp+1], pl[ks], &vh[2]);
            }
        }
    }

    const float rl0 = 1.f / l0, rl1 = 1.f / l1;
    const int gr = b*SEQ + qt*128 + warprow + (lane >> 2);
    #pragma unroll
    for (int nt = 0; nt < 8; nt++) {
        const int gc = hoff + nt*8 + (lane & 3)*2;
        const size_t i0 = (size_t)gr * EMBED + gc;
        const size_t i1 = i0 + (size_t)8 * EMBED;
        uint32_t hp, lp;
        pack_split(o[nt][0]*rl0, o[nt][1]*rl0, hp, lp);
        *(uint32_t*)(Ohi + i0) = hp;  *(uint32_t*)(Olo + i0) = lp;
        pack_split(o[nt][2]*rl1, o[nt][3]*rl1, hp, lp);
        *(uint32_t*)(Ohi + i1) = hp;  *(uint32_t*)(Olo + i1) = lp;
    }
}

// ------------------------- host ---------------------------------------------
extern "C" void kernel_launch(void* const* d_in, const int* in_sizes, int n_in,
                              void* d_out, int out_size)
{
    const float* x     = (const float*)d_in[0];
    const float* ln1_g = (const float*)d_in[1];
    const float* ln1_b = (const float*)d_in[2];
    const float* w_qkv = (const float*)d_in[3];
    const float* w_out = (const float*)d_in[4];
    const float* b_out = (const float*)d_in[5];
    const float* ln2_g = (const float*)d_in[6];
    const float* ln2_b = (const float*)d_in[7];
    const float* w1    = (const float*)d_in[8];
    const float* b1    = (const float*)d_in[9];
    const float* w2    = (const float*)d_in[10];
    const float* b2    = (const float*)d_in[11];
    float* out = (float*)d_out;

    float *h32, *x2, *sa_h, *sa_h2, *sa_mid, *sb_qkv, *sb_w1, *sb_w2, *cmq, *cm1, *cm2;
    int8_t *hq1,*hq2,*wq8a,*wq8b,*w18a,*w18b,*w28a,*w28b,*h2q1,*h2q2,*mq1,*mq2;
    bf16 *woutT_hi,*woutT_lo,*qkv_hi,*qkv_lo,*attn_hi,*attn_lo,*mid_hi,*mid_lo;
    cudaGetSymbolAddress((void**)&h32, g_h32);
    cudaGetSymbolAddress((void**)&hq1, g_hq1);     cudaGetSymbolAddress((void**)&hq2, g_hq2);
    cudaGetSymbolAddress((void**)&sa_h, g_sa_h);
    cudaGetSymbolAddress((void**)&wq8a, g_wqkv8a); cudaGetSymbolAddress((void**)&wq8b, g_wqkv8b);
    cudaGetSymbolAddress((void**)&sb_qkv, g_sb_qkv);
    cudaGetSymbolAddress((void**)&woutT_hi, g_woutT_hi); cudaGetSymbolAddress((void**)&woutT_lo, g_woutT_lo);
    cudaGetSymbolAddress((void**)&w18a, g_w18a);   cudaGetSymbolAddress((void**)&w18b, g_w18b);
    cudaGetSymbolAddress((void**)&sb_w1, g_sb_w1);
    cudaGetSymbolAddress((void**)&w28a, g_w28a);   cudaGetSymbolAddress((void**)&w28b, g_w28b);
    cudaGetSymbolAddress((void**)&sb_w2, g_sb_w2);
    cudaGetSymbolAddress((void**)&qkv_hi, g_qkv_hi);   cudaGetSymbolAddress((void**)&qkv_lo, g_qkv_lo);
    cudaGetSymbolAddress((void**)&attn_hi, g_attn_hi); cudaGetSymbolAddress((void**)&attn_lo, g_attn_lo);
    cudaGetSymbolAddress((void**)&x2, g_x2);
    cudaGetSymbolAddress((void**)&h2q1, g_h2q1);   cudaGetSymbolAddress((void**)&h2q2, g_h2q2);
    cudaGetSymbolAddress((void**)&sa_h2, g_sa_h2);
    cudaGetSymbolAddress((void**)&mid_hi, g_mid_hi);   cudaGetSymbolAddress((void**)&mid_lo, g_mid_lo);
    cudaGetSymbolAddress((void**)&mq1, g_midq1);   cudaGetSymbolAddress((void**)&mq2, g_midq2);
    cudaGetSymbolAddress((void**)&sa_mid, g_sa_mid);
    cudaGetSymbolAddress((void**)&cmq, g_cm_qkv);
    cudaGetSymbolAddress((void**)&cm1, g_cm_w1);
    cudaGetSymbolAddress((void**)&cm2, g_cm_w2);

    const int SMG = 2 * 4 * 128 * 80;     // 81920
    const int SMF = 110592;
    cudaFuncSetAttribute(gemm_i8<0>, cudaFuncAttributeMaxDynamicSharedMemorySize, SMG);
    cudaFuncSetAttribute(gemm_i8<1>, cudaFuncAttributeMaxDynamicSharedMemorySize, SMG);
    cudaFuncSetAttribute(gemm_i8<2>, cudaFuncAttributeMaxDynamicSharedMemorySize, SMG);
    cudaFuncSetAttribute(gemm_wout,  cudaFuncAttributeMaxDynamicSharedMemorySize, SMG);
    cudaFuncSetAttribute(flash_attn, cudaFuncAttributeMaxDynamicSharedMemorySize, SMF);

    // weight prep: colmax -> int8 planes (+ bf16 planes for w_out)
    zcm<<<(QKVW+255)/256, 256>>>(cmq, QKVW);
    zcm<<<(MLPD+255)/256, 256>>>(cm1, MLPD);
    zcm<<<(EMBED+255)/256, 256>>>(cm2, EMBED);
    wcolmax<<<dim3(QKVW/256, EMBED/256), 256>>>(w_qkv, cmq, EMBED, QKVW);
    wcolmax<<<dim3(MLPD/256, EMBED/256), 256>>>(w1, cm1, EMBED, MLPD);
    wcolmax<<<dim3(EMBED/256, MLPD/256), 256>>>(w2, cm2, MLPD, EMBED);
    tconv8<<<dim3(QKVW/32, EMBED/32), dim3(32,8)>>>(w_qkv, cmq, wq8a, wq8b, sb_qkv, EMBED, QKVW);
    tconv8<<<dim3(MLPD/32, EMBED/32), dim3(32,8)>>>(w1, cm1, w18a, w18b, sb_w1, EMBED, MLPD);
    tconv8<<<dim3(EMBED/32, MLPD/32), dim3(32,8)>>>(w2, cm2, w28a, w28b, sb_w2, MLPD, EMBED);
    tconv<<<dim3(EMBED/32, EMBED/32), dim3(32,8)>>>(w_out, woutT_hi, woutT_lo, EMBED, EMBED);

    // 1) h = LN1(x) -> int8 planes + fp32 copy
    ln8<<<ROWS, 256>>>(x, ln1_g, ln1_b, h32, hq1, hq2, sa_h);

    // 2) qkv = h @ w_qkv (int8) -> bf16 hi/lo, Q cols pre-scaled 1/8
    gemm_i8<0><<<dim3(QKVW/128, ROWS/128), 256, SMG>>>(
        hq1, hq2, sa_h, EMBED, wq8a, wq8b, sb_qkv, EMBED,
        nullptr, qkv_hi, qkv_lo, QKVW, nullptr, nullptr, EMBED);

    // 3) fused flash attention (bf16 hi/lo)
    flash_attn<<<dim3(SEQ/128, BH), 256, SMF>>>(qkv_hi, qkv_lo, attn_hi, attn_lo);

    // 4) x2 = x + h + attn @ w_out + b_out   (bf16 hi/lo path)
    gemm_wout<<<dim3(EMBED/128, ROWS/128), 256, SMG>>>(
        attn_hi, attn_lo, EMBED, woutT_hi, woutT_lo, EMBED,
        x2, EMBED, b_out, x, h32, EMBED);

    // 5) h2 = LN2(x2) -> int8 planes
    ln8<<<ROWS, 256>>>(x2, ln2_g, ln2_b, nullptr, h2q1, h2q2, sa_h2);

    // 6) mid = gelu(h2 @ w1 + b1) (int8) -> bf16 hi/lo
    gemm_i8<1><<<dim3(MLPD/128, ROWS/128), 256, SMG>>>(
        h2q1, h2q2, sa_h2, EMBED, w18a, w18b, sb_w1, EMBED,
        nullptr, mid_hi, mid_lo, MLPD, b1, nullptr, EMBED);

    // 6b) quantize mid -> int8 planes
    quant8<<<ROWS, 256>>>(mid_hi, mid_lo, mq1, mq2, sa_mid);

    // 7) out = x2 + mid @ w2 + b2 (int8)
    gemm_i8<2><<<dim3(EMBED/128, ROWS/128), 256, SMG>>>(
        mq1, mq2, sa_mid, MLPD, w28a, w28b, sb_w2, MLPD,
        out, nullptr, nullptr, EMBED, b2, x2, MLPD);
}

// round 9
// speedup vs baseline: 1.5973x; 1.5973x over previous
#include <cuda_runtime.h>
#include <cuda_bf16.h>
#include <math.h>
#include <stdint.h>

#define EMBED 768
#define HEADS 12
#define HD    64
#define MLPD  3072
#define BATCH 4
#define SEQ   1024
#define ROWS  (BATCH*SEQ)
#define QKVW  (3*EMBED)
#define BH    (BATCH*HEADS)

typedef __nv_bfloat16 bf16;

// ------------------------- scratch ------------------------------------------
__device__ float  g_h32 [ROWS*EMBED];
__device__ int8_t g_hq1[ROWS*EMBED],  g_hq2[ROWS*EMBED];
__device__ float  g_sa_h[ROWS];
__device__ int8_t g_wqkv8a[QKVW*EMBED], g_wqkv8b[QKVW*EMBED];
__device__ float  g_sb_qkv[QKVW];
__device__ bf16   g_woutT_hi[EMBED*EMBED], g_woutT_lo[EMBED*EMBED];
__device__ int8_t g_w18a[MLPD*EMBED], g_w18b[MLPD*EMBED];
__device__ float  g_sb_w1[MLPD];
__device__ int8_t g_w28a[EMBED*MLPD], g_w28b[EMBED*MLPD];
__device__ float  g_sb_w2[EMBED];
__device__ bf16   g_qkv_hi[ROWS*QKVW], g_qkv_lo[ROWS*QKVW];
__device__ bf16   g_attn_hi[ROWS*EMBED], g_attn_lo[ROWS*EMBED];
__device__ float  g_x2[ROWS*EMBED];
__device__ int8_t g_h2q1[ROWS*EMBED], g_h2q2[ROWS*EMBED];
__device__ float  g_sa_h2[ROWS];
__device__ bf16   g_mid_hi[ROWS*MLPD], g_mid_lo[ROWS*MLPD];
__device__ int8_t g_midq1[ROWS*MLPD], g_midq2[ROWS*MLPD];
__device__ float  g_sa_mid[ROWS];
__device__ float  g_cm_qkv[QKVW], g_cm_w1[MLPD], g_cm_w2[EMBED];

// ------------------------- helpers ------------------------------------------
__device__ __forceinline__ uint32_t smem_u32(const void* p){
    uint32_t a;
    asm("{ .reg .u64 t; cvta.to.shared.u64 t, %1; cvt.u32.u64 %0, t; }" : "=r"(a) : "l"(p));
    return a;
}
__device__ __forceinline__ void split_bf(float v, bf16& h, bf16& l){
    h = __float2bfloat16(v);
    l = __float2bfloat16(v - __bfloat162float(h));
}
__device__ __forceinline__ void cp16(uint32_t dst, const void* src){
    asm volatile("cp.async.cg.shared.global [%0], [%1], 16;" :: "r"(dst), "l"(src));
}
__device__ __forceinline__ void ldsm4(uint32_t* r, uint32_t a){
    asm volatile("ldmatrix.sync.aligned.m8n8.x4.shared.b16 {%0,%1,%2,%3}, [%4];"
        : "=r"(r[0]),"=r"(r[1]),"=r"(r[2]),"=r"(r[3]) : "r"(a));
}
__device__ __forceinline__ void ldsm4t(uint32_t* r, uint32_t a){
    asm volatile("ldmatrix.sync.aligned.m8n8.x4.trans.shared.b16 {%0,%1,%2,%3}, [%4];"
        : "=r"(r[0]),"=r"(r[1]),"=r"(r[2]),"=r"(r[3]) : "r"(a));
}
__device__ __forceinline__ void ldsm2(uint32_t* r, uint32_t a){
    asm volatile("ldmatrix.sync.aligned.m8n8.x2.shared.b16 {%0,%1}, [%2];"
        : "=r"(r[0]),"=r"(r[1]) : "r"(a));
}
__device__ __forceinline__ void mma16816(float* c, const uint32_t* a, const uint32_t* b){
    asm volatile("mma.sync.aligned.m16n8k16.row.col.f32.bf16.bf16.f32 "
        "{%0,%1,%2,%3}, {%4,%5,%6,%7}, {%8,%9}, {%0,%1,%2,%3};"
        : "+f"(c[0]),"+f"(c[1]),"+f"(c[2]),"+f"(c[3])
        : "r"(a[0]),"r"(a[1]),"r"(a[2]),"r"(a[3]), "r"(b[0]),"r"(b[1]));
}
__device__ __forceinline__ void imma16832(int* c, const uint32_t* a, const uint32_t* b){
    asm volatile("mma.sync.aligned.m16n8k32.row.col.s32.s8.s8.s32 "
        "{%0,%1,%2,%3}, {%4,%5,%6,%7}, {%8,%9}, {%0,%1,%2,%3};"
        : "+r"(c[0]),"+r"(c[1]),"+r"(c[2]),"+r"(c[3])
        : "r"(a[0]),"r"(a[1]),"r"(a[2]),"r"(a[3]), "r"(b[0]),"r"(b[1]));
}
__device__ __forceinline__ uint32_t pack_bf2(bf16 a, bf16 b){
    return (uint32_t)__bfloat16_as_ushort(a) | ((uint32_t)__bfloat16_as_ushort(b) << 16);
}
__device__ __forceinline__ void pack_split(float x, float y, uint32_t& hp, uint32_t& lp){
    bf16 hx, lx, hy, ly;
    split_bf(x, hx, lx); split_bf(y, hy, ly);
    hp = pack_bf2(hx, hy);
    lp = pack_bf2(lx, ly);
}
__device__ __forceinline__ void quant2(float v, float inv_s, float s, int8_t& q1, int8_t& q2){
    int a = __float2int_rn(v * inv_s);
    a = max(-127, min(127, a));
    float r = v - s * (float)a;
    int c = __float2int_rn(r * inv_s * 128.f);
    c = max(-127, min(127, c));
    q1 = (int8_t)a; q2 = (int8_t)c;
}

// ------------------------- weight prep --------------------------------------
__global__ void zcm(float* a, int n){
    int i = blockIdx.x*256 + threadIdx.x;
    if (i < n) a[i] = 0.f;
}
__global__ void wcolmax(const float* __restrict__ W, float* __restrict__ cm, int K, int N){
    const int n = blockIdx.x*256 + threadIdx.x;
    const int k0 = blockIdx.y*64;
    float m = 0.f;
    for (int k = k0; k < k0 + 64 && k < K; k++)
        m = fmaxf(m, fabsf(W[(size_t)k*N + n]));
    atomicMax((unsigned int*)&cm[n], __float_as_uint(m));
}
__global__ void tconv8(const float* __restrict__ W, const float* __restrict__ cm,
                       int8_t* __restrict__ T1, int8_t* __restrict__ T2,
                       float* __restrict__ sb, int K, int N)
{
    __shared__ float s[32][33];
    const int n0 = blockIdx.x * 32, k0 = blockIdx.y * 32;
    const int tx = threadIdx.x, ty = threadIdx.y;
    #pragma unroll
    for (int i = 0; i < 4; i++)
        s[ty + i*8][tx] = W[(size_t)(k0 + ty + i*8) * N + n0 + tx];
    __syncthreads();
    #pragma unroll
    for (int i = 0; i < 4; i++) {
        const int n = ty + i*8;
        const float cmv = fmaxf(cm[n0+n], 1e-30f);
        const float sc = cmv / 127.f, inv = 127.f / cmv;
        int8_t q1, q2;
        quant2(s[tx][n], inv, sc, q1, q2);
        const size_t o = (size_t)(n0 + n) * K + k0 + tx;
        T1[o] = q1; T2[o] = q2;
        if (k0 == 0 && tx == 0) sb[n0+n] = sc;
    }
}
// bf16 hi/lo transpose (w_out only)
__global__ void tconv(const float* __restrict__ W, bf16* __restrict__ Thi, bf16* __restrict__ Tlo,
                      int K, int N)
{
    __shared__ float s[32][33];
    const int n0 = blockIdx.x * 32, k0 = blockIdx.y * 32;
    const int tx = threadIdx.x, ty = threadIdx.y;
    #pragma unroll
    for (int i = 0; i < 4; i++)
        s[ty + i*8][tx] = W[(size_t)(k0 + ty + i*8) * N + n0 + tx];
    __syncthreads();
    #pragma unroll
    for (int i = 0; i < 4; i++) {
        const int n = ty + i*8;
        bf16 h, l; split_bf(s[tx][n], h, l);
        const size_t o = (size_t)(n0 + n) * K + k0 + tx;
        Thi[o] = h; Tlo[o] = l;
    }
}

// ------------------------- LayerNorm -> int8 planes -------------------------
__global__ __launch_bounds__(256) void ln8(const float* __restrict__ x,
                                           const float* __restrict__ g,
                                           const float* __restrict__ b,
                                           float* __restrict__ out32,
                                           int8_t* __restrict__ q1p,
                                           int8_t* __restrict__ q2p,
                                           float* __restrict__ sa)
{
    const int row = blockIdx.x;
    const int t = threadIdx.x;
    const float* xr = x + (size_t)row * EMBED;
    float v0 = xr[t], v1 = xr[t+256], v2 = xr[t+512];
    float s = v0+v1+v2, sq = v0*v0+v1*v1+v2*v2;
    #pragma unroll
    for (int off = 16; off; off >>= 1) {
        s  += __shfl_xor_sync(0xffffffffu, s,  off);
        sq += __shfl_xor_sync(0xffffffffu, sq, off);
    }
    __shared__ float red[24];
    const int w = t >> 5;
    if ((t & 31) == 0) { red[w] = s; red[8+w] = sq; }
    __syncthreads();
    float tot = 0.f, totq = 0.f;
    #pragma unroll
    for (int i = 0; i < 8; i++) { tot += red[i]; totq += red[8+i]; }
    const float mu = tot * (1.f/768.f);
    const float var = totq * (1.f/768.f) - mu*mu;
    const float rstd = rsqrtf(fmaxf(var, 0.f) + 1e-5f);
    const size_t o = (size_t)row * EMBED;
    float y[3];
    #pragma unroll
    for (int i = 0; i < 3; i++) {
        const int c = t + i*256;
        const float v = (i==0?v0:(i==1?v1:v2));
        y[i] = (v - mu) * rstd * g[c] + b[c];
        if (out32) out32[o + c] = y[i];
    }
    float am = fmaxf(fabsf(y[0]), fmaxf(fabsf(y[1]), fabsf(y[2])));
    #pragma unroll
    for (int off = 16; off; off >>= 1) am = fmaxf(am, __shfl_xor_sync(0xffffffffu, am, off));
    if ((t & 31) == 0) red[16+w] = am;
    __syncthreads();
    float bm = red[16];
    #pragma unroll
    for (int i = 1; i < 8; i++) bm = fmaxf(bm, red[16+i]);
    bm = fmaxf(bm, 1e-30f);
    const float sc = bm / 127.f, inv = 127.f / bm;
    #pragma unroll
    for (int i = 0; i < 3; i++) {
        int8_t q1, q2;
        quant2(y[i], inv, sc, q1, q2);
        q1p[o + t + i*256] = q1; q2p[o + t + i*256] = q2;
    }
    if (t == 0) sa[row] = sc;
}

// ------------------------- mid (bf16 hi/lo) -> int8 planes ------------------
__global__ __launch_bounds__(256) void quant8(const bf16* __restrict__ hi, const bf16* __restrict__ lo,
                                              int8_t* __restrict__ q1p, int8_t* __restrict__ q2p,
                                              float* __restrict__ sa)
{
    const int row = blockIdx.x;
    const int t = threadIdx.x;
    const size_t base = (size_t)row * MLPD;
    float v[12];
    float am = 0.f;
    #pragma unroll
    for (int i = 0; i < 12; i++) {
        const int c = t + i*256;
        v[i] = __bfloat162float(hi[base+c]) + __bfloat162float(lo[base+c]);
        am = fmaxf(am, fabsf(v[i]));
    }
    #pragma unroll
    for (int off = 16; off; off >>= 1) am = fmaxf(am, __shfl_xor_sync(0xffffffffu, am, off));
    __shared__ float red[8];
    const int w = t >> 5;
    if ((t & 31) == 0) red[w] = am;
    __syncthreads();
    float bm = red[0];
    #pragma unroll
    for (int i = 1; i < 8; i++) bm = fmaxf(bm, red[i]);
    bm = fmaxf(bm, 1e-30f);
    const float sc = bm / 127.f, inv = 127.f / bm;
    #pragma unroll
    for (int i = 0; i < 12; i++) {
        int8_t q1, q2;
        quant2(v[i], inv, sc, q1, q2);
        q1p[base + t + i*256] = q1; q2p[base + t + i*256] = q2;
    }
    if (t == 0) sa[row] = sc;
}

// ------------------------- int8 dual-plane GEMM (full-K int accum) ----------
// C[m][n] = sum_k A[m][k]B[n][k], A/B = s*(q1 + q2/128). Per k32: 3 IMMA into
// PERSISTENT int32 accumulators d1 (q1q1) and d23 (q1q2 + q2q1); fp32 fold
// happens ONCE in the epilogue. Overflow-safe: |d1|<=127^2*3072<2^31.
// EPI 0: qkv (split bf16, cols<768 *0.125)  1: split(gelu(+bias))
// EPI 2: f32 +bias+add1
template<int EPI>
__global__ void __launch_bounds__(256, 1) gemm_i8(
    const int8_t* __restrict__ Aq1, const int8_t* __restrict__ Aq2, const float* __restrict__ sa, int lda,
    const int8_t* __restrict__ Bq1, const int8_t* __restrict__ Bq2, const float* __restrict__ sb, int ldb,
    float* __restrict__ C, bf16* __restrict__ Chi, bf16* __restrict__ Clo, int ldc,
    const float* __restrict__ bias, const float* __restrict__ add1,
    int K)
{
    constexpr int RS  = 80;
    constexpr int SP  = 128 * RS;     // 10240 per plane (128 rows x 64B + pad)
    constexpr int BUF = 4 * SP;       // A1 A2 B1 B2

    extern __shared__ char sm[];
    const uint32_t smb = smem_u32(sm);
    const int tid  = threadIdx.x;
    const int wid  = tid >> 5, lane = tid & 31;
    const int warp_m = wid & 1, warp_n = wid >> 1;
    const int rowBase = blockIdx.y * 128;
    const int colBase = blockIdx.x * 128;

    int d1[4][4][4], d23[4][4][4];
    #pragma unroll
    for (int mt = 0; mt < 4; mt++)
        #pragma unroll
        for (int nt = 0; nt < 4; nt++)
            #pragma unroll
            for (int i = 0; i < 4; i++) { d1[mt][nt][i] = 0; d23[mt][nt][i] = 0; }

    auto load_chunk = [&](int c) {
        const uint32_t st = smb + (c & 1)*BUF;
        const int k0 = c * 64;
        #pragma unroll
        for (int i = 0; i < 8; i++) {
            const int t = tid + i*256;
            const int pl = t >> 9, rem = t & 511, rr = rem >> 2, cg = rem & 3;
            const int8_t* base = (pl==0) ? Aq1 : (pl==1) ? Aq2 : (pl==2) ? Bq1 : Bq2;
            const int rb = (pl < 2) ? rowBase : colBase;
            const int ld = (pl < 2) ? lda : ldb;
            cp16(st + pl*SP + rr*RS + cg*16, base + (size_t)(rb + rr)*ld + k0 + cg*16);
        }
        asm volatile("cp.async.commit_group;");
    };

    load_chunk(0);
    const int NC = K / 64;
    for (int c = 0; c < NC; ++c) {
        asm volatile("cp.async.wait_group 0;" ::: "memory");
        __syncthreads();
        if (c + 1 < NC) load_chunk(c + 1);

        const uint32_t st = smb + (c & 1)*BUF;
        #pragma unroll
        for (int ks = 0; ks < 2; ks++) {
            uint32_t b1[4][2], b2[4][2];
            #pragma unroll
            for (int nt = 0; nt < 4; nt++) {
                const int row = warp_n*32 + nt*8 + (lane & 7);
                const uint32_t ad = st + 2*SP + row*RS + ks*32 + ((lane >> 3) & 1)*16;
                ldsm2(b1[nt], ad);
                ldsm2(b2[nt], ad + SP);
            }
            #pragma unroll
            for (int mt = 0; mt < 4; mt++) {
                const int row = warp_m*64 + mt*16 + (lane & 15);
                const uint32_t aad = st + row*RS + ks*32 + (lane >> 4)*16;
                uint32_t a1[4], a2[4];
                ldsm4(a1, aad);
                ldsm4(a2, aad + SP);
                #pragma unroll
                for (int nt = 0; nt < 4; nt++) {
                    imma16832(d1[mt][nt],  a1, b1[nt]);
                    imma16832(d23[mt][nt], a1, b2[nt]);
                    imma16832(d23[mt][nt], a2, b1[nt]);
                }
            }
        }
    }

    #pragma unroll
    for (int mt = 0; mt < 4; mt++) {
        #pragma unroll
        for (int nt = 0; nt < 4; nt++) {
            const int gr0 = rowBase + warp_m*64 + mt*16 + (lane >> 2);
            const int gc  = colBase + warp_n*32 + nt*8 + (lane & 3)*2;
            const float sb0 = sb[gc], sb1 = sb[gc+1];
            #pragma unroll
            for (int half = 0; half < 2; half++) {
                const int gr = gr0 + half*8;
                const float sar = sa[gr];
                const size_t idx = (size_t)gr * ldc + gc;
                float v0 = ((float)d1[mt][nt][half*2+0] + (float)d23[mt][nt][half*2+0]*0.0078125f) * sar * sb0;
                float v1 = ((float)d1[mt][nt][half*2+1] + (float)d23[mt][nt][half*2+1]*0.0078125f) * sar * sb1;
                if (EPI == 2) {
                    v0 += bias[gc+0] + add1[idx+0];
                    v1 += bias[gc+1] + add1[idx+1];
                    *(float2*)(C + idx) = make_float2(v0, v1);
                } else {
                    if (EPI == 1) {
                        v0 += bias[gc+0];
                        v1 += bias[gc+1];
                        v0 = 0.5f * v0 * (1.f + erff(v0 * 0.70710678118654752f));
                        v1 = 0.5f * v1 * (1.f + erff(v1 * 0.70710678118654752f));
                    }
                    if (EPI == 0 && gc < EMBED) { v0 *= 0.125f; v1 *= 0.125f; }
                    uint32_t hp, lp;
                    pack_split(v0, v1, hp, lp);
                    *(uint32_t*)(Chi + idx) = hp;
                    *(uint32_t*)(Clo + idx) = lp;
                }
            }
        }
    }
}

// ------------------------- bf16 hi/lo GEMM (wout) ---------------------------
__global__ void __launch_bounds__(256, 2) gemm_wout(
    const bf16* __restrict__ Ahi, const bf16* __restrict__ Alo, int lda,
    const bf16* __restrict__ Bhi, const bf16* __restrict__ Blo, int ldb,
    float* __restrict__ C, int ldc,
    const float* __restrict__ bias, const float* __restrict__ add1, const float* __restrict__ add2,
    int K)
{
    constexpr int RS  = 80;
    constexpr int SA  = 128 * RS;
    constexpr int BUF = 4 * SA;

    extern __shared__ char sm[];
    const uint32_t smb = smem_u32(sm);
    const int tid  = threadIdx.x;
    const int wid  = tid >> 5, lane = tid & 31;
    const int warp_m = wid & 1, warp_n = wid >> 1;
    const int rowBase = blockIdx.y * 128;
    const int colBase = blockIdx.x * 128;

    float acc[4][4][4];
    #pragma unroll
    for (int mt = 0; mt < 4; mt++)
        #pragma unroll
        for (int nt = 0; nt < 4; nt++)
            #pragma unroll
            for (int i = 0; i < 4; i++) acc[mt][nt][i] = 0.f;

    auto load_chunk = [&](int c) {
        const uint32_t st = smb + (c & 1)*BUF;
        const int k0 = c * 32;
        #pragma unroll
        for (int i = 0; i < 4; i++) {
            const int t = tid + i*256;
            const int plane = t >> 9, rr = (t >> 2) & 127, cg = t & 3;
            const bf16* src = (plane ? Alo : Ahi) + (size_t)(rowBase + rr) * lda + k0 + cg*8;
            cp16(st + plane*SA + rr*RS + cg*16, src);
        }
        #pragma unroll
        for (int i = 0; i < 4; i++) {
            const int t = tid + i*256;
            const int plane = t >> 9, rr = (t >> 2) & 127, cg = t & 3;
            const bf16* src = (plane ? Blo : Bhi) + (size_t)(colBase + rr) * ldb + k0 + cg*8;
            cp16(st + 2*SA + plane*SA + rr*RS + cg*16, src);
        }
        asm volatile("cp.async.commit_group;");
    };

    load_chunk(0);
    const int NC = K / 32;
    for (int c = 0; c < NC; ++c) {
        asm volatile("cp.async.wait_group 0;" ::: "memory");
        __syncthreads();
        if (c + 1 < NC) load_chunk(c + 1);

        const uint32_t st = smb + (c & 1)*BUF;
        #pragma unroll
        for (int ks = 0; ks < 2; ks++) {
            uint32_t bh[4][2], bl[4][2];
            #pragma unroll
            for (int nt = 0; nt < 4; nt++) {
                const int row = warp_n*32 + nt*8 + (lane & 7);
                const uint32_t ad = st + 2*SA + row*RS + ks*32 + ((lane >> 3) & 1)*16;
                ldsm2(bh[nt], ad);
                ldsm2(bl[nt], ad + SA);
            }
            #pragma unroll
            for (int mt = 0; mt < 4; mt++) {
                const int row = warp_m*64 + mt*16 + (lane & 15);
                const uint32_t aad = st + row*RS + ks*32 + (lane >> 4)*16;
                uint32_t ah[4], al[4];
                ldsm4(ah, aad);
                ldsm4(al, aad + SA);
                #pragma unroll
                for (int nt = 0; nt < 4; nt++) {
                    mma16816(acc[mt][nt], ah, bh[nt]);
                    mma16816(acc[mt][nt], ah, bl[nt]);
                    mma16816(acc[mt][nt], al, bh[nt]);
                }
            }
        }
    }

    #pragma unroll
    for (int mt = 0; mt < 4; mt++) {
        #pragma unroll
        for (int nt = 0; nt < 4; nt++) {
            const int gr0 = rowBase + warp_m*64 + mt*16 + (lane >> 2);
            const int gc  = colBase + warp_n*32 + nt*8 + (lane & 3)*2;
            #pragma unroll
            for (int half = 0; half < 2; half++) {
                const int gr = gr0 + half*8;
                const size_t idx = (size_t)gr * ldc + gc;
                float v0 = acc[mt][nt][half*2 + 0] + bias[gc+0] + add1[idx+0] + add2[idx+0];
                float v1 = acc[mt][nt][half*2 + 1] + bias[gc+1] + add1[idx+1] + add2[idx+1];
                *(float2*)(C + idx) = make_float2(v0, v1);
            }
        }
    }
}

// ------------------------- fused flash attention ----------------------------
__global__ void __launch_bounds__(256) flash_attn(
    const bf16* __restrict__ qh_g, const bf16* __restrict__ ql_g,
    bf16* __restrict__ Ohi, bf16* __restrict__ Olo)
{
    extern __shared__ char sm[];
    const uint32_t smb = smem_u32(sm);
    const int tid = threadIdx.x, lane = tid & 31, wid = tid >> 5;
    const int qt = blockIdx.x;
    const int b  = blockIdx.y / HEADS, h = blockIdx.y % HEADS;
    const size_t gbase = (size_t)b * SEQ * QKVW;
    const int hoff = h * HD;

    #pragma unroll
    for (int i = 0; i < 8; i++) {
        const int t = tid + i*256;
        const int plane = t >> 10, rem = t & 1023, r = rem >> 3, cg = rem & 7;
        const bf16* src = (plane ? ql_g : qh_g) + gbase + (size_t)(qt*128 + r)*QKVW + hoff + cg*8;
        cp16(smb + plane*18432 + (uint32_t)(r*144 + cg*16), src);
    }
    auto load_kv = [&](int j) {
        const uint32_t dst = smb + 36864 + (j & 1)*36864;
        #pragma unroll
        for (int i = 0; i < 8; i++) {
            const int t = tid + i*256;
            const int q4 = t >> 9, rem = t & 511, r = rem >> 3, cg = rem & 7;
            const bf16* src = ((q4 & 1) ? ql_g : qh_g) + gbase
                + (size_t)(j*64 + r)*QKVW + EMBED + (q4 >> 1)*EMBED + hoff + cg*8;
            cp16(dst + (uint32_t)(q4*9216 + r*144 + cg*16), src);
        }
        asm volatile("cp.async.commit_group;");
    };
    load_kv(0);

    const int warprow = wid * 16;
    float m0 = -1e30f, m1 = -1e30f, l0 = 0.f, l1 = 0.f;
    float o[8][4];
    #pragma unroll
    for (int nt = 0; nt < 8; nt++)
        #pragma unroll
        for (int i = 0; i < 4; i++) o[nt][i] = 0.f;

    for (int j = 0; j < 16; j++) {
        asm volatile("cp.async.wait_group 0;" ::: "memory");
        __syncthreads();
        if (j < 15) load_kv(j + 1);
        const uint32_t st = smb + 36864 + (j & 1)*36864;

        float s[8][4];
        #pragma unroll
        for (int nt = 0; nt < 8; nt++)
            #pragma unroll
            for (int i = 0; i < 4; i++) s[nt][i] = 0.f;
        #pragma unroll
        for (int ks = 0; ks < 4; ks++) {
            uint32_t qh[4], ql[4];
            const uint32_t qa = smb + (uint32_t)((warprow + (lane & 15))*144 + ks*32 + (lane >> 4)*16);
            ldsm4(qh, qa);
            ldsm4(ql, qa + 18432);
            #pragma unroll
            for (int nt = 0; nt < 8; nt++) {
                uint32_t kh[2], kl[2];
                const uint32_t ka = st + (uint32_t)((nt*8 + (lane & 7))*144 + ks*32 + ((lane >> 3) & 1)*16);
                ldsm2(kh, ka);
                ldsm2(kl, ka + 9216);
                mma16816(s[nt], qh, kh);
                mma16816(s[nt], qh, kl);
                mma16816(s[nt], ql, kh);
            }
        }

        float mt0 = s[0][0], mt1 = s[0][2];
        #pragma unroll
        for (int nt = 0; nt < 8; nt++) {
            mt0 = fmaxf(mt0, fmaxf(s[nt][0], s[nt][1]));
            mt1 = fmaxf(mt1, fmaxf(s[nt][2], s[nt][3]));
        }
        mt0 = fmaxf(mt0, __shfl_xor_sync(0xffffffffu, mt0, 1));
        mt0 = fmaxf(mt0, __shfl_xor_sync(0xffffffffu, mt0, 2));
        mt1 = fmaxf(mt1, __shfl_xor_sync(0xffffffffu, mt1, 1));
        mt1 = fmaxf(mt1, __shfl_xor_sync(0xffffffffu, mt1, 2));
        const float mn0 = fmaxf(m0, mt0), mn1 = fmaxf(m1, mt1);
        const float a0 = __expf(m0 - mn0), a1 = __expf(m1 - mn1);
        float rs0 = 0.f, rs1 = 0.f;
        #pragma unroll
        for (int nt = 0; nt < 8; nt++) {
            s[nt][0] = __expf(s[nt][0] - mn0); rs0 += s[nt][0];
            s[nt][1] = __expf(s[nt][1] - mn0); rs0 += s[nt][1];
            s[nt][2] = __expf(s[nt][2] - mn1); rs1 += s[nt][2];
            s[nt][3] = __expf(s[nt][3] - mn1); rs1 += s[nt][3];
        }
        rs0 += __shfl_xor_sync(0xffffffffu, rs0, 1);
        rs0 += __shfl_xor_sync(0xffffffffu, rs0, 2);
        rs1 += __shfl_xor_sync(0xffffffffu, rs1, 1);
        rs1 += __shfl_xor_sync(0xffffffffu, rs1, 2);
        l0 = l0 * a0 + rs0;  l1 = l1 * a1 + rs1;
        m0 = mn0;  m1 = mn1;
        #pragma unroll
        for (int nt = 0; nt < 8; nt++) {
            o[nt][0] *= a0; o[nt][1] *= a0;
            o[nt][2] *= a1; o[nt][3] *= a1;
        }

        uint32_t ph[4][4], pl[4][4];
        #pragma unroll
        for (int ks = 0; ks < 4; ks++) {
            pack_split(s[2*ks][0],   s[2*ks][1],   ph[ks][0], pl[ks][0]);
            pack_split(s[2*ks][2],   s[2*ks][3],   ph[ks][1], pl[ks][1]);
            pack_split(s[2*ks+1][0], s[2*ks+1][1], ph[ks][2], pl[ks][2]);
            pack_split(s[2*ks+1][2], s[2*ks+1][3], ph[ks][3], pl[ks][3]);
        }

        #pragma unroll
        for (int ks = 0; ks < 4; ks++) {
            #pragma unroll
            for (int ntp = 0; ntp < 4; ntp++) {
                uint32_t vh[4], vl[4];
                const uint32_t va = st + 18432
                    + (uint32_t)((ks*16 + ((lane >> 3) & 1)*8 + (lane & 7))*144
                                 + ntp*32 + (lane >> 4)*16);
                ldsm4t(vh, va);
                ldsm4t(vl, va + 9216);
                mma16816(o[2*ntp],   ph[ks], &vh[0]);
                mma16816(o[2*ntp],   ph[ks], &vl[0]);
                mma16816(o[2*ntp],   pl[ks], &vh[0]);
                mma16816(o[2*ntp+1], ph[ks], &vh[2]);
                mma16816(o[2*ntp+1], ph[ks], &vl[2]);
                mma16816(o[2*ntp+1], pl[ks], &vh[2]);
            }
        }
    }

    const float rl0 = 1.f / l0, rl1 = 1.f / l1;
    const int gr = b*SEQ + qt*128 + warprow + (lane >> 2);
    #pragma unroll
    for (int nt = 0; nt < 8; nt++) {
        const int gc = hoff + nt*8 + (lane & 3)*2;
        const size_t i0 = (size_t)gr * EMBED + gc;
        const size_t i1 = i0 + (size_t)8 * EMBED;
        uint32_t hp, lp;
        pack_split(o[nt][0]*rl0, o[nt][1]*rl0, hp, lp);
        *(uint32_t*)(Ohi + i0) = hp;  *(uint32_t*)(Olo + i0) = lp;
        pack_split(o[nt][2]*rl1, o[nt][3]*rl1, hp, lp);
        *(uint32_t*)(Ohi + i1) = hp;  *(uint32_t*)(Olo + i1) = lp;
    }
}

// ------------------------- host ---------------------------------------------
extern "C" void kernel_launch(void* const* d_in, const int* in_sizes, int n_in,
                              void* d_out, int out_size)
{
    const float* x     = (const float*)d_in[0];
    const float* ln1_g = (const float*)d_in[1];
    const float* ln1_b = (const float*)d_in[2];
    const float* w_qkv = (const float*)d_in[3];
    const float* w_out = (const float*)d_in[4];
    const float* b_out = (const float*)d_in[5];
    const float* ln2_g = (const float*)d_in[6];
    const float* ln2_b = (const float*)d_in[7];
    const float* w1    = (const float*)d_in[8];
    const float* b1    = (const float*)d_in[9];
    const float* w2    = (const float*)d_in[10];
    const float* b2    = (const float*)d_in[11];
    float* out = (float*)d_out;

    float *h32, *x2, *sa_h, *sa_h2, *sa_mid, *sb_qkv, *sb_w1, *sb_w2, *cmq, *cm1, *cm2;
    int8_t *hq1,*hq2,*wq8a,*wq8b,*w18a,*w18b,*w28a,*w28b,*h2q1,*h2q2,*mq1,*mq2;
    bf16 *woutT_hi,*woutT_lo,*qkv_hi,*qkv_lo,*attn_hi,*attn_lo,*mid_hi,*mid_lo;
    cudaGetSymbolAddress((void**)&h32, g_h32);
    cudaGetSymbolAddress((void**)&hq1, g_hq1);     cudaGetSymbolAddress((void**)&hq2, g_hq2);
    cudaGetSymbolAddress((void**)&sa_h, g_sa_h);
    cudaGetSymbolAddress((void**)&wq8a, g_wqkv8a); cudaGetSymbolAddress((void**)&wq8b, g_wqkv8b);
    cudaGetSymbolAddress((void**)&sb_qkv, g_sb_qkv);
    cudaGetSymbolAddress((void**)&woutT_hi, g_woutT_hi); cudaGetSymbolAddress((void**)&woutT_lo, g_woutT_lo);
    cudaGetSymbolAddress((void**)&w18a, g_w18a);   cudaGetSymbolAddress((void**)&w18b, g_w18b);
    cudaGetSymbolAddress((void**)&sb_w1, g_sb_w1);
    cudaGetSymbolAddress((void**)&w28a, g_w28a);   cudaGetSymbolAddress((void**)&w28b, g_w28b);
    cudaGetSymbolAddress((void**)&sb_w2, g_sb_w2);
    cudaGetSymbolAddress((void**)&qkv_hi, g_qkv_hi);   cudaGetSymbolAddress((void**)&qkv_lo, g_qkv_lo);
    cudaGetSymbolAddress((void**)&attn_hi, g_attn_hi); cudaGetSymbolAddress((void**)&attn_lo, g_attn_lo);
    cudaGetSymbolAddress((void**)&x2, g_x2);
    cudaGetSymbolAddress((void**)&h2q1, g_h2q1);   cudaGetSymbolAddress((void**)&h2q2, g_h2q2);
    cudaGetSymbolAddress((void**)&sa_h2, g_sa_h2);
    cudaGetSymbolAddress((void**)&mid_hi, g_mid_hi);   cudaGetSymbolAddress((void**)&mid_lo, g_mid_lo);
    cudaGetSymbolAddress((void**)&mq1, g_midq1);   cudaGetSymbolAddress((void**)&mq2, g_midq2);
    cudaGetSymbolAddress((void**)&sa_mid, g_sa_mid);
    cudaGetSymbolAddress((void**)&cmq, g_cm_qkv);
    cudaGetSymbolAddress((void**)&cm1, g_cm_w1);
    cudaGetSymbolAddress((void**)&cm2, g_cm_w2);

    const int SMG = 2 * 4 * 128 * 80;     // 81920
    const int SMF = 110592;
    cudaFuncSetAttribute(gemm_i8<0>, cudaFuncAttributeMaxDynamicSharedMemorySize, SMG);
    cudaFuncSetAttribute(gemm_i8<1>, cudaFuncAttributeMaxDynamicSharedMemorySize, SMG);
    cudaFuncSetAttribute(gemm_i8<2>, cudaFuncAttributeMaxDynamicSharedMemorySize, SMG);
    cudaFuncSetAttribute(gemm_wout,  cudaFuncAttributeMaxDynamicSharedMemorySize, SMG);
    cudaFuncSetAttribute(flash_attn, cudaFuncAttributeMaxDynamicSharedMemorySize, SMF);

    // weight prep: colmax -> int8 planes (+ bf16 planes for w_out)
    zcm<<<(QKVW+255)/256, 256>>>(cmq, QKVW);
    zcm<<<(MLPD+255)/256, 256>>>(cm1, MLPD);
    zcm<<<(EMBED+255)/256, 256>>>(cm2, EMBED);
    wcolmax<<<dim3(QKVW/256, EMBED/64), 256>>>(w_qkv, cmq, EMBED, QKVW);
    wcolmax<<<dim3(MLPD/256, EMBED/64), 256>>>(w1, cm1, EMBED, MLPD);
    wcolmax<<<dim3(EMBED/256, MLPD/64), 256>>>(w2, cm2, MLPD, EMBED);
    tconv8<<<dim3(QKVW/32, EMBED/32), dim3(32,8)>>>(w_qkv, cmq, wq8a, wq8b, sb_qkv, EMBED, QKVW);
    tconv8<<<dim3(MLPD/32, EMBED/32), dim3(32,8)>>>(w1, cm1, w18a, w18b, sb_w1, EMBED, MLPD);
    tconv8<<<dim3(EMBED/32, MLPD/32), dim3(32,8)>>>(w2, cm2, w28a, w28b, sb_w2, MLPD, EMBED);
    tconv<<<dim3(EMBED/32, EMBED/32), dim3(32,8)>>>(w_out, woutT_hi, woutT_lo, EMBED, EMBED);

    // 1) h = LN1(x) -> int8 planes + fp32 copy
    ln8<<<ROWS, 256>>>(x, ln1_g, ln1_b, h32, hq1, hq2, sa_h);

    // 2) qkv = h @ w_qkv (int8) -> bf16 hi/lo, Q cols pre-scaled 1/8
    gemm_i8<0><<<dim3(QKVW/128, ROWS/128), 256, SMG>>>(
        hq1, hq2, sa_h, EMBED, wq8a, wq8b, sb_qkv, EMBED,
        nullptr, qkv_hi, qkv_lo, QKVW, nullptr, nullptr, EMBED);

    // 3) fused flash attention (bf16 hi/lo)
    flash_attn<<<dim3(SEQ/128, BH), 256, SMF>>>(qkv_hi, qkv_lo, attn_hi, attn_lo);

    // 4) x2 = x + h + attn @ w_out + b_out   (bf16 hi/lo path)
    gemm_wout<<<dim3(EMBED/128, ROWS/128), 256, SMG>>>(
        attn_hi, attn_lo, EMBED, woutT_hi, woutT_lo, EMBED,
        x2, EMBED, b_out, x, h32, EMBED);

    // 5) h2 = LN2(x2) -> int8 planes
    ln8<<<ROWS, 256>>>(x2, ln2_g, ln2_b, nullptr, h2q1, h2q2, sa_h2);

    // 6) mid = gelu(h2 @ w1 + b1) (int8) -> bf16 hi/lo
    gemm_i8<1><<<dim3(MLPD/128, ROWS/128), 256, SMG>>>(
        h2q1, h2q2, sa_h2, EMBED, w18a, w18b, sb_w1, EMBED,
        nullptr, mid_hi, mid_lo, MLPD, b1, nullptr, EMBED);

    // 6b) quantize mid -> int8 planes
    quant8<<<ROWS, 256>>>(mid_hi, mid_lo, mq1, mq2, sa_mid);

    // 7) out = x2 + mid @ w2 + b2 (int8)
    gemm_i8<2><<<dim3(EMBED/128, ROWS/128), 256, SMG>>>(
        mq1, mq2, sa_mid, MLPD, w28a, w28b, sb_w2, MLPD,
        out, nullptr, nullptr, EMBED, b2, x2, MLPD);
}

// round 10
// speedup vs baseline: 4.5122x; 2.8248x over previous
#include <cuda_runtime.h>
#include <cuda_bf16.h>
#include <cuda_fp16.h>
#include <math.h>
#include <stdint.h>

#define EMBED 768
#define HEADS 12
#define HD    64
#define MLPD  3072
#define BATCH 4
#define SEQ   1024
#define ROWS  (BATCH*SEQ)
#define QKVW  (3*EMBED)
#define BH    (BATCH*HEADS)

typedef __nv_bfloat16 bf16;

// ------------------------- scratch ------------------------------------------
__device__ float  g_h32 [ROWS*EMBED];
__device__ bf16   g_h_hi[ROWS*EMBED],  g_h_lo[ROWS*EMBED];
__device__ bf16   g_wqkvT_hi[QKVW*EMBED], g_wqkvT_lo[QKVW*EMBED];
__device__ bf16   g_woutT_hi[EMBED*EMBED], g_woutT_lo[EMBED*EMBED];
__device__ __half g_w1T16[MLPD*EMBED];
__device__ __half g_w2T16[EMBED*MLPD];
__device__ bf16   g_qkv_hi[ROWS*QKVW],  g_qkv_lo[ROWS*QKVW];
__device__ bf16   g_attn_hi[ROWS*EMBED], g_attn_lo[ROWS*EMBED];
__device__ float  g_x2[ROWS*EMBED];
__device__ __half g_h2_hi[ROWS*EMBED], g_h2_lo[ROWS*EMBED];
__device__ __half g_mid16[ROWS*MLPD];

// ------------------------- helpers ------------------------------------------
__device__ __forceinline__ uint32_t smem_u32(const void* p){
    uint32_t a;
    asm("{ .reg .u64 t; cvta.to.shared.u64 t, %1; cvt.u32.u64 %0, t; }" : "=r"(a) : "l"(p));
    return a;
}
__device__ __forceinline__ void split_bf(float v, bf16& h, bf16& l){
    h = __float2bfloat16(v);
    l = __float2bfloat16(v - __bfloat162float(h));
}
__device__ __forceinline__ void split_h(float v, __half& h, __half& l){
    h = __float2half(v);
    l = __float2half(v - __half2float(h));
}
__device__ __forceinline__ void cp16(uint32_t dst, const void* src){
    asm volatile("cp.async.cg.shared.global [%0], [%1], 16;" :: "r"(dst), "l"(src));
}
__device__ __forceinline__ void ldsm4(uint32_t* r, uint32_t a){
    asm volatile("ldmatrix.sync.aligned.m8n8.x4.shared.b16 {%0,%1,%2,%3}, [%4];"
        : "=r"(r[0]),"=r"(r[1]),"=r"(r[2]),"=r"(r[3]) : "r"(a));
}
__device__ __forceinline__ void ldsm4t(uint32_t* r, uint32_t a){
    asm volatile("ldmatrix.sync.aligned.m8n8.x4.trans.shared.b16 {%0,%1,%2,%3}, [%4];"
        : "=r"(r[0]),"=r"(r[1]),"=r"(r[2]),"=r"(r[3]) : "r"(a));
}
__device__ __forceinline__ void ldsm2(uint32_t* r, uint32_t a){
    asm volatile("ldmatrix.sync.aligned.m8n8.x2.shared.b16 {%0,%1}, [%2];"
        : "=r"(r[0]),"=r"(r[1]) : "r"(a));
}
__device__ __forceinline__ void mma16816(float* c, const uint32_t* a, const uint32_t* b){
    asm volatile("mma.sync.aligned.m16n8k16.row.col.f32.bf16.bf16.f32 "
        "{%0,%1,%2,%3}, {%4,%5,%6,%7}, {%8,%9}, {%0,%1,%2,%3};"
        : "+f"(c[0]),"+f"(c[1]),"+f"(c[2]),"+f"(c[3])
        : "r"(a[0]),"r"(a[1]),"r"(a[2]),"r"(a[3]), "r"(b[0]),"r"(b[1]));
}
__device__ __forceinline__ void mma16816h(float* c, const uint32_t* a, const uint32_t* b){
    asm volatile("mma.sync.aligned.m16n8k16.row.col.f32.f16.f16.f32 "
        "{%0,%1,%2,%3}, {%4,%5,%6,%7}, {%8,%9}, {%0,%1,%2,%3};"
        : "+f"(c[0]),"+f"(c[1]),"+f"(c[2]),"+f"(c[3])
        : "r"(a[0]),"r"(a[1]),"r"(a[2]),"r"(a[3]), "r"(b[0]),"r"(b[1]));
}
__device__ __forceinline__ uint32_t pack_bf2(bf16 a, bf16 b){
    return (uint32_t)__bfloat16_as_ushort(a) | ((uint32_t)__bfloat16_as_ushort(b) << 16);
}
__device__ __forceinline__ void pack_split(float x, float y, uint32_t& hp, uint32_t& lp){
    bf16 hx, lx, hy, ly;
    split_bf(x, hx, lx); split_bf(y, hy, ly);
    hp = pack_bf2(hx, hy);
    lp = pack_bf2(lx, ly);
}
__device__ __forceinline__ uint32_t pack_h2(__half a, __half b){
    return (uint32_t)__half_as_ushort(a) | ((uint32_t)__half_as_ushort(b) << 16);
}

// ------------------------- weight transforms --------------------------------
// bf16 hi/lo transpose (w_qkv, w_out)
__global__ void tconv(const float* __restrict__ W, bf16* __restrict__ Thi, bf16* __restrict__ Tlo,
                      int K, int N)
{
    __shared__ float s[32][33];
    const int n0 = blockIdx.x * 32, k0 = blockIdx.y * 32;
    const int tx = threadIdx.x, ty = threadIdx.y;
    #pragma unroll
    for (int i = 0; i < 4; i++)
        s[ty + i*8][tx] = W[(size_t)(k0 + ty + i*8) * N + n0 + tx];
    __syncthreads();
    #pragma unroll
    for (int i = 0; i < 4; i++) {
        const int n = ty + i*8;
        bf16 h, l; split_bf(s[tx][n], h, l);
        const size_t o = (size_t)(n0 + n) * K + k0 + tx;
        Thi[o] = h; Tlo[o] = l;
    }
}
// single-fp16 transpose (w1, w2)
__global__ void tconv16(const float* __restrict__ W, __half* __restrict__ T, int K, int N)
{
    __shared__ float s[32][33];
    const int n0 = blockIdx.x * 32, k0 = blockIdx.y * 32;
    const int tx = threadIdx.x, ty = threadIdx.y;
    #pragma unroll
    for (int i = 0; i < 4; i++)
        s[ty + i*8][tx] = W[(size_t)(k0 + ty + i*8) * N + n0 + tx];
    __syncthreads();
    #pragma unroll
    for (int i = 0; i < 4; i++) {
        const int n = ty + i*8;
        T[(size_t)(n0 + n) * K + k0 + tx] = __float2half(s[tx][n]);
    }
}

// ------------------------- LayerNorms ---------------------------------------
__global__ __launch_bounds__(256) void ln_kernel(const float* __restrict__ x,
                                                 const float* __restrict__ g,
                                                 const float* __restrict__ b,
                                                 float* __restrict__ out32,
                                                 bf16* __restrict__ ohi,
                                                 bf16* __restrict__ olo)
{
    const int row = blockIdx.x;
    const int t = threadIdx.x;
    const float* xr = x + (size_t)row * EMBED;
    float v0 = xr[t], v1 = xr[t+256], v2 = xr[t+512];
    float s = v0+v1+v2, sq = v0*v0+v1*v1+v2*v2;
    #pragma unroll
    for (int off = 16; off; off >>= 1) {
        s  += __shfl_xor_sync(0xffffffffu, s,  off);
        sq += __shfl_xor_sync(0xffffffffu, sq, off);
    }
    __shared__ float red[16];
    const int w = t >> 5;
    if ((t & 31) == 0) { red[w] = s; red[8+w] = sq; }
    __syncthreads();
    float tot = 0.f, totq = 0.f;
    #pragma unroll
    for (int i = 0; i < 8; i++) { tot += red[i]; totq += red[8+i]; }
    const float mu = tot * (1.f/768.f);
    const float var = totq * (1.f/768.f) - mu*mu;
    const float rstd = rsqrtf(fmaxf(var, 0.f) + 1e-5f);
    const size_t o = (size_t)row * EMBED;
    #pragma unroll
    for (int i = 0; i < 3; i++) {
        const int c = t + i*256;
        const float v = (i==0?v0:(i==1?v1:v2));
        const float y = (v - mu) * rstd * g[c] + b[c];
        if (out32) out32[o + c] = y;
        bf16 h, l; split_bf(y, h, l);
        ohi[o + c] = h; olo[o + c] = l;
    }
}
// LN2: fp16 hi/lo outputs
__global__ __launch_bounds__(256) void ln16(const float* __restrict__ x,
                                            const float* __restrict__ g,
                                            const float* __restrict__ b,
                                            __half* __restrict__ ohi,
                                            __half* __restrict__ olo)
{
    const int row = blockIdx.x;
    const int t = threadIdx.x;
    const float* xr = x + (size_t)row * EMBED;
    float v0 = xr[t], v1 = xr[t+256], v2 = xr[t+512];
    float s = v0+v1+v2, sq = v0*v0+v1*v1+v2*v2;
    #pragma unroll
    for (int off = 16; off; off >>= 1) {
        s  += __shfl_xor_sync(0xffffffffu, s,  off);
        sq += __shfl_xor_sync(0xffffffffu, sq, off);
    }
    __shared__ float red[16];
    const int w = t >> 5;
    if ((t & 31) == 0) { red[w] = s; red[8+w] = sq; }
    __syncthreads();
    float tot = 0.f, totq = 0.f;
    #pragma unroll
    for (int i = 0; i < 8; i++) { tot += red[i]; totq += red[8+i]; }
    const float mu = tot * (1.f/768.f);
    const float var = totq * (1.f/768.f) - mu*mu;
    const float rstd = rsqrtf(fmaxf(var, 0.f) + 1e-5f);
    const size_t o = (size_t)row * EMBED;
    #pragma unroll
    for (int i = 0; i < 3; i++) {
        const int c = t + i*256;
        const float v = (i==0?v0:(i==1?v1:v2));
        const float y = (v - mu) * rstd * g[c] + b[c];
        __half h, l; split_h(y, h, l);
        ohi[o + c] = h; olo[o + c] = l;
    }
}

// ------------------------- bf16 hi/lo 3-MMA GEMM ----------------------------
// EPI 1: hi/lo split out (QS: cols<768 scaled 0.125)  EPI 2: f32 +bias+add1+add2
template<int EPI, bool QS>
__global__ void __launch_bounds__(256, 2) gemm_mma(
    const bf16* __restrict__ Ahi, const bf16* __restrict__ Alo, int lda,
    const bf16* __restrict__ Bhi, const bf16* __restrict__ Blo, int ldb,
    float* __restrict__ C, bf16* __restrict__ Chi, bf16* __restrict__ Clo, int ldc,
    const float* __restrict__ bias, const float* __restrict__ add1, const float* __restrict__ add2,
    int K)
{
    constexpr int RS  = 80;
    constexpr int SA  = 128 * RS;
    constexpr int BUF = 4 * SA;

    extern __shared__ char sm[];
    const uint32_t smb = smem_u32(sm);
    const int tid  = threadIdx.x;
    const int wid  = tid >> 5, lane = tid & 31;
    const int warp_m = wid & 1, warp_n = wid >> 1;
    const int rowBase = blockIdx.y * 128;
    const int colBase = blockIdx.x * 128;

    float acc[4][4][4];
    #pragma unroll
    for (int mt = 0; mt < 4; mt++)
        #pragma unroll
        for (int nt = 0; nt < 4; nt++)
            #pragma unroll
            for (int i = 0; i < 4; i++) acc[mt][nt][i] = 0.f;

    auto load_chunk = [&](int c) {
        const uint32_t st = smb + (c & 1)*BUF;
        const int k0 = c * 32;
        #pragma unroll
        for (int i = 0; i < 4; i++) {
            const int t = tid + i*256;
            const int plane = t >> 9, rr = (t >> 2) & 127, cg = t & 3;
            const bf16* src = (plane ? Alo : Ahi) + (size_t)(rowBase + rr) * lda + k0 + cg*8;
            cp16(st + plane*SA + rr*RS + cg*16, src);
        }
        #pragma unroll
        for (int i = 0; i < 4; i++) {
            const int t = tid + i*256;
            const int plane = t >> 9, rr = (t >> 2) & 127, cg = t & 3;
            const bf16* src = (plane ? Blo : Bhi) + (size_t)(colBase + rr) * ldb + k0 + cg*8;
            cp16(st + 2*SA + plane*SA + rr*RS + cg*16, src);
        }
        asm volatile("cp.async.commit_group;");
    };

    load_chunk(0);
    const int NC = K / 32;
    for (int c = 0; c < NC; ++c) {
        asm volatile("cp.async.wait_group 0;" ::: "memory");
        __syncthreads();
        if (c + 1 < NC) load_chunk(c + 1);

        const uint32_t st = smb + (c & 1)*BUF;
        #pragma unroll
        for (int ks = 0; ks < 2; ks++) {
            uint32_t bh[4][2], bl[4][2];
            #pragma unroll
            for (int nt = 0; nt < 4; nt++) {
                const int row = warp_n*32 + nt*8 + (lane & 7);
                const uint32_t ad = st + 2*SA + row*RS + ks*32 + ((lane >> 3) & 1)*16;
                ldsm2(bh[nt], ad);
                ldsm2(bl[nt], ad + SA);
            }
            #pragma unroll
            for (int mt = 0; mt < 4; mt++) {
                const int row = warp_m*64 + mt*16 + (lane & 15);
                const uint32_t aad = st + row*RS + ks*32 + (lane >> 4)*16;
                uint32_t ah[4], al[4];
                ldsm4(ah, aad);
                ldsm4(al, aad + SA);
                #pragma unroll
                for (int nt = 0; nt < 4; nt++) {
                    mma16816(acc[mt][nt], ah, bh[nt]);
                    mma16816(acc[mt][nt], ah, bl[nt]);
                    mma16816(acc[mt][nt], al, bh[nt]);
                }
            }
        }
    }

    #pragma unroll
    for (int mt = 0; mt < 4; mt++) {
        #pragma unroll
        for (int nt = 0; nt < 4; nt++) {
            const int gr0 = rowBase + warp_m*64 + mt*16 + (lane >> 2);
            const int gc  = colBase + warp_n*32 + nt*8 + (lane & 3)*2;
            #pragma unroll
            for (int half = 0; half < 2; half++) {
                const int gr = gr0 + half*8;
                const size_t idx = (size_t)gr * ldc + gc;
                float v0 = acc[mt][nt][half*2 + 0];
                float v1 = acc[mt][nt][half*2 + 1];
                if (EPI == 2) {
                    v0 += bias[gc+0] + add1[idx+0] + add2[idx+0];
                    v1 += bias[gc+1] + add1[idx+1] + add2[idx+1];
                    *(float2*)(C + idx) = make_float2(v0, v1);
                } else {
                    if (QS && gc < EMBED) { v0 *= 0.125f; v1 *= 0.125f; }
                    uint32_t hp, lp;
                    pack_split(v0, v1, hp, lp);
                    *(uint32_t*)(Chi + idx) = hp;
                    *(uint32_t*)(Clo + idx) = lp;
                }
            }
        }
    }
}

// ------------------------- fp16 GEMM (NA A-planes, single-B) ----------------
// EPI 3: mid = gelu(acc + bias) -> single fp16
// EPI 4: C = acc + bias + add1 (f32)
template<int NA, int EPI>
__global__ void __launch_bounds__(256, 2) gemm_h(
    const __half* __restrict__ A1, const __half* __restrict__ A2, int lda,
    const __half* __restrict__ B, int ldb,
    float* __restrict__ C, __half* __restrict__ Ch, int ldc,
    const float* __restrict__ bias, const float* __restrict__ add1,
    int K)
{
    constexpr int RS  = 80;
    constexpr int SP  = 128 * RS;
    constexpr int NP  = NA + 1;
    constexpr int BUF = NP * SP;

    extern __shared__ char sm[];
    const uint32_t smb = smem_u32(sm);
    const int tid  = threadIdx.x;
    const int wid  = tid >> 5, lane = tid & 31;
    const int warp_m = wid & 1, warp_n = wid >> 1;
    const int rowBase = blockIdx.y * 128;
    const int colBase = blockIdx.x * 128;

    float acc[4][4][4];
    #pragma unroll
    for (int mt = 0; mt < 4; mt++)
        #pragma unroll
        for (int nt = 0; nt < 4; nt++)
            #pragma unroll
            for (int i = 0; i < 4; i++) acc[mt][nt][i] = 0.f;

    auto load_chunk = [&](int c) {
        const uint32_t st = smb + (c & 1)*BUF;
        const int k0 = c * 32;
        #pragma unroll
        for (int i = 0; i < NP*2; i++) {
            const int t = tid + i*256;
            const int pl = t >> 9, rem = t & 511, rr = rem >> 2, cg = rem & 3;
            const __half* src;
            if (pl < NA) src = (pl ? A2 : A1) + (size_t)(rowBase + rr) * lda + k0 + cg*8;
            else         src = B + (size_t)(colBase + rr) * ldb + k0 + cg*8;
            cp16(st + pl*SP + rr*RS + cg*16, src);
        }
        asm volatile("cp.async.commit_group;");
    };

    load_chunk(0);
    const int NC = K / 32;
    for (int c = 0; c < NC; ++c) {
        asm volatile("cp.async.wait_group 0;" ::: "memory");
        __syncthreads();
        if (c + 1 < NC) load_chunk(c + 1);

        const uint32_t st = smb + (c & 1)*BUF;
        #pragma unroll
        for (int ks = 0; ks < 2; ks++) {
            uint32_t bfr[4][2];
            #pragma unroll
            for (int nt = 0; nt < 4; nt++) {
                const int row = warp_n*32 + nt*8 + (lane & 7);
                ldsm2(bfr[nt], st + NA*SP + row*RS + ks*32 + ((lane >> 3) & 1)*16);
            }
            #pragma unroll
            for (int mt = 0; mt < 4; mt++) {
                const int row = warp_m*64 + mt*16 + (lane & 15);
                const uint32_t aad = st + row*RS + ks*32 + (lane >> 4)*16;
                uint32_t ah[4], al[4];
                ldsm4(ah, aad);
                if (NA == 2) ldsm4(al, aad + SP);
                #pragma unroll
                for (int nt = 0; nt < 4; nt++) {
                    mma16816h(acc[mt][nt], ah, bfr[nt]);
                    if (NA == 2) mma16816h(acc[mt][nt], al, bfr[nt]);
                }
            }
        }
    }

    #pragma unroll
    for (int mt = 0; mt < 4; mt++) {
        #pragma unroll
        for (int nt = 0; nt < 4; nt++) {
            const int gr0 = rowBase + warp_m*64 + mt*16 + (lane >> 2);
            const int gc  = colBase + warp_n*32 + nt*8 + (lane & 3)*2;
            #pragma unroll
            for (int half = 0; half < 2; half++) {
                const int gr = gr0 + half*8;
                const size_t idx = (size_t)gr * ldc + gc;
                float v0 = acc[mt][nt][half*2 + 0] + bias[gc+0];
                float v1 = acc[mt][nt][half*2 + 1] + bias[gc+1];
                if (EPI == 3) {
                    v0 = 0.5f * v0 * (1.f + erff(v0 * 0.70710678118654752f));
                    v1 = 0.5f * v1 * (1.f + erff(v1 * 0.70710678118654752f));
                    *(uint32_t*)(Ch + idx) = pack_h2(__float2half(v0), __float2half(v1));
                } else {
                    v0 += add1[idx+0];
                    v1 += add1[idx+1];
                    *(float2*)(C + idx) = make_float2(v0, v1);
                }
            }
        }
    }
}

// ------------------------- fused flash attention (bf16 hi/lo) ---------------
__global__ void __launch_bounds__(256) flash_attn(
    const bf16* __restrict__ qh_g, const bf16* __restrict__ ql_g,
    bf16* __restrict__ Ohi, bf16* __restrict__ Olo)
{
    extern __shared__ char sm[];
    const uint32_t smb = smem_u32(sm);
    const int tid = threadIdx.x, lane = tid & 31, wid = tid >> 5;
    const int qt = blockIdx.x;
    const int b  = blockIdx.y / HEADS, h = blockIdx.y % HEADS;
    const size_t gbase = (size_t)b * SEQ * QKVW;
    const int hoff = h * HD;

    #pragma unroll
    for (int i = 0; i < 8; i++) {
        const int t = tid + i*256;
        const int plane = t >> 10, rem = t & 1023, r = rem >> 3, cg = rem & 7;
        const bf16* src = (plane ? ql_g : qh_g) + gbase + (size_t)(qt*128 + r)*QKVW + hoff + cg*8;
        cp16(smb + plane*18432 + (uint32_t)(r*144 + cg*16), src);
    }
    auto load_kv = [&](int j) {
        const uint32_t dst = smb + 36864 + (j & 1)*36864;
        #pragma unroll
        for (int i = 0; i < 8; i++) {
            const int t = tid + i*256;
            const int q4 = t >> 9, rem = t & 511, r = rem >> 3, cg = rem & 7;
            const bf16* src = ((q4 & 1) ? ql_g : qh_g) + gbase
                + (size_t)(j*64 + r)*QKVW + EMBED + (q4 >> 1)*EMBED + hoff + cg*8;
            cp16(dst + (uint32_t)(q4*9216 + r*144 + cg*16), src);
        }
        asm volatile("cp.async.commit_group;");
    };
    load_kv(0);

    const int warprow = wid * 16;
    float m0 = -1e30f, m1 = -1e30f, l0 = 0.f, l1 = 0.f;
    float o[8][4];
    #pragma unroll
    for (int nt = 0; nt < 8; nt++)
        #pragma unroll
        for (int i = 0; i < 4; i++) o[nt][i] = 0.f;

    for (int j = 0; j < 16; j++) {
        asm volatile("cp.async.wait_group 0;" ::: "memory");
        __syncthreads();
        if (j < 15) load_kv(j + 1);
        const uint32_t st = smb + 36864 + (j & 1)*36864;

        float s[8][4];
        #pragma unroll
        for (int nt = 0; nt < 8; nt++)
            #pragma unroll
            for (int i = 0; i < 4; i++) s[nt][i] = 0.f;
        #pragma unroll
        for (int ks = 0; ks < 4; ks++) {
            uint32_t qh[4], ql[4];
            const uint32_t qa = smb + (uint32_t)((warprow + (lane & 15))*144 + ks*32 + (lane >> 4)*16);
            ldsm4(qh, qa);
            ldsm4(ql, qa + 18432);
            #pragma unroll
            for (int nt = 0; nt < 8; nt++) {
                uint32_t kh[2], kl[2];
                const uint32_t ka = st + (uint32_t)((nt*8 + (lane & 7))*144 + ks*32 + ((lane >> 3) & 1)*16);
                ldsm2(kh, ka);
                ldsm2(kl, ka + 9216);
                mma16816(s[nt], qh, kh);
                mma16816(s[nt], qh, kl);
                mma16816(s[nt], ql, kh);
            }
        }

        float mt0 = s[0][0], mt1 = s[0][2];
        #pragma unroll
        for (int nt = 0; nt < 8; nt++) {
            mt0 = fmaxf(mt0, fmaxf(s[nt][0], s[nt][1]));
            mt1 = fmaxf(mt1, fmaxf(s[nt][2], s[nt][3]));
        }
        mt0 = fmaxf(mt0, __shfl_xor_sync(0xffffffffu, mt0, 1));
        mt0 = fmaxf(mt0, __shfl_xor_sync(0xffffffffu, mt0, 2));
        mt1 = fmaxf(mt1, __shfl_xor_sync(0xffffffffu, mt1, 1));
        mt1 = fmaxf(mt1, __shfl_xor_sync(0xffffffffu, mt1, 2));
        const float mn0 = fmaxf(m0, mt0), mn1 = fmaxf(m1, mt1);
        const float a0 = __expf(m0 - mn0), a1 = __expf(m1 - mn1);
        float rs0 = 0.f, rs1 = 0.f;
        #pragma unroll
        for (int nt = 0; nt < 8; nt++) {
            s[nt][0] = __expf(s[nt][0] - mn0); rs0 += s[nt][0];
            s[nt][1] = __expf(s[nt][1] - mn0); rs0 += s[nt][1];
            s[nt][2] = __expf(s[nt][2] - mn1); rs1 += s[nt][2];
            s[nt][3] = __expf(s[nt][3] - mn1); rs1 += s[nt][3];
        }
        rs0 += __shfl_xor_sync(0xffffffffu, rs0, 1);
        rs0 += __shfl_xor_sync(0xffffffffu, rs0, 2);
        rs1 += __shfl_xor_sync(0xffffffffu, rs1, 1);
        rs1 += __shfl_xor_sync(0xffffffffu, rs1, 2);
        l0 = l0 * a0 + rs0;  l1 = l1 * a1 + rs1;
        m0 = mn0;  m1 = mn1;
        #pragma unroll
        for (int nt = 0; nt < 8; nt++) {
            o[nt][0] *= a0; o[nt][1] *= a0;
            o[nt][2] *= a1; o[nt][3] *= a1;
        }

        uint32_t ph[4][4], pl[4][4];
        #pragma unroll
        for (int ks = 0; ks < 4; ks++) {
            pack_split(s[2*ks][0],   s[2*ks][1],   ph[ks][0], pl[ks][0]);
            pack_split(s[2*ks][2],   s[2*ks][3],   ph[ks][1], pl[ks][1]);
            pack_split(s[2*ks+1][0], s[2*ks+1][1], ph[ks][2], pl[ks][2]);
            pack_split(s[2*ks+1][2], s[2*ks+1][3], ph[ks][3], pl[ks][3]);
        }

        #pragma unroll
        for (int ks = 0; ks < 4; ks++) {
            #pragma unroll
            for (int ntp = 0; ntp < 4; ntp++) {
                uint32_t vh[4], vl[4];
                const uint32_t va = st + 18432
                    + (uint32_t)((ks*16 + ((lane >> 3) & 1)*8 + (lane & 7))*144
                                 + ntp*32 + (lane >> 4)*16);
                ldsm4t(vh, va);
                ldsm4t(vl, va + 9216);
                mma16816(o[2*ntp],   ph[ks], &vh[0]);
                mma16816(o[2*ntp],   ph[ks], &vl[0]);
                mma16816(o[2*ntp],   pl[ks], &vh[0]);
                mma16816(o[2*ntp+1], ph[ks], &vh[2]);
                mma16816(o[2*ntp+1], ph[ks], &vl[2]);
                mma16816(o[2*ntp+1], pl[ks], &vh[2]);
            }
        }
    }

    const float rl0 = 1.f / l0, rl1 = 1.f / l1;
    const int gr = b*SEQ + qt*128 + warprow + (lane >> 2);
    #pragma unroll
    for (int nt = 0; nt < 8; nt++) {
        const int gc = hoff + nt*8 + (lane & 3)*2;
        const size_t i0 = (size_t)gr * EMBED + gc;
        const size_t i1 = i0 + (size_t)8 * EMBED;
        uint32_t hp, lp;
        pack_split(o[nt][0]*rl0, o[nt][1]*rl0, hp, lp);
        *(uint32_t*)(Ohi + i0) = hp;  *(uint32_t*)(Olo + i0) = lp;
        pack_split(o[nt][2]*rl1, o[nt][3]*rl1, hp, lp);
        *(uint32_t*)(Ohi + i1) = hp;  *(uint32_t*)(Olo + i1) = lp;
    }
}

// ------------------------- host ---------------------------------------------
extern "C" void kernel_launch(void* const* d_in, const int* in_sizes, int n_in,
                              void* d_out, int out_size)
{
    const float* x     = (const float*)d_in[0];
    const float* ln1_g = (const float*)d_in[1];
    const float* ln1_b = (const float*)d_in[2];
    const float* w_qkv = (const float*)d_in[3];
    const float* w_out = (const float*)d_in[4];
    const float* b_out = (const float*)d_in[5];
    const float* ln2_g = (const float*)d_in[6];
    const float* ln2_b = (const float*)d_in[7];
    const float* w1    = (const float*)d_in[8];
    const float* b1    = (const float*)d_in[9];
    const float* w2    = (const float*)d_in[10];
    const float* b2    = (const float*)d_in[11];
    float* out = (float*)d_out;

    float *h32, *x2;
    bf16 *h_hi,*h_lo,*wqkvT_hi,*wqkvT_lo,*woutT_hi,*woutT_lo;
    bf16 *qkv_hi,*qkv_lo,*attn_hi,*attn_lo;
    __half *w1T16,*w2T16,*h2_hi,*h2_lo,*mid16;
    cudaGetSymbolAddress((void**)&h32, g_h32);
    cudaGetSymbolAddress((void**)&h_hi, g_h_hi);       cudaGetSymbolAddress((void**)&h_lo, g_h_lo);
    cudaGetSymbolAddress((void**)&wqkvT_hi, g_wqkvT_hi); cudaGetSymbolAddress((void**)&wqkvT_lo, g_wqkvT_lo);
    cudaGetSymbolAddress((void**)&woutT_hi, g_woutT_hi); cudaGetSymbolAddress((void**)&woutT_lo, g_woutT_lo);
    cudaGetSymbolAddress((void**)&w1T16, g_w1T16);
    cudaGetSymbolAddress((void**)&w2T16, g_w2T16);
    cudaGetSymbolAddress((void**)&qkv_hi, g_qkv_hi);   cudaGetSymbolAddress((void**)&qkv_lo, g_qkv_lo);
    cudaGetSymbolAddress((void**)&attn_hi, g_attn_hi); cudaGetSymbolAddress((void**)&attn_lo, g_attn_lo);
    cudaGetSymbolAddress((void**)&x2, g_x2);
    cudaGetSymbolAddress((void**)&h2_hi, g_h2_hi);     cudaGetSymbolAddress((void**)&h2_lo, g_h2_lo);
    cudaGetSymbolAddress((void**)&mid16, g_mid16);

    const int SMG  = 2 * 4 * 128 * 80;     // 81920  (bf16 4-plane)
    const int SMH3 = 2 * 3 * 128 * 80;     // 61440  (fp16 3-plane)
    const int SMH2 = 2 * 2 * 128 * 80;     // 40960  (fp16 2-plane)
    const int SMF  = 110592;
    cudaFuncSetAttribute(gemm_mma<1,true >, cudaFuncAttributeMaxDynamicSharedMemorySize, SMG);
    cudaFuncSetAttribute(gemm_mma<2,false>, cudaFuncAttributeMaxDynamicSharedMemorySize, SMG);
    cudaFuncSetAttribute(gemm_h<2,3>,       cudaFuncAttributeMaxDynamicSharedMemorySize, SMH3);
    cudaFuncSetAttribute(gemm_h<1,4>,       cudaFuncAttributeMaxDynamicSharedMemorySize, SMH2);
    cudaFuncSetAttribute(flash_attn,        cudaFuncAttributeMaxDynamicSharedMemorySize, SMF);

    // weight prep
    tconv<<<dim3(QKVW/32, EMBED/32), dim3(32,8)>>>(w_qkv, wqkvT_hi, wqkvT_lo, EMBED, QKVW);
    tconv<<<dim3(EMBED/32, EMBED/32), dim3(32,8)>>>(w_out, woutT_hi, woutT_lo, EMBED, EMBED);
    tconv16<<<dim3(MLPD/32, EMBED/32), dim3(32,8)>>>(w1, w1T16, EMBED, MLPD);
    tconv16<<<dim3(EMBED/32, MLPD/32), dim3(32,8)>>>(w2, w2T16, MLPD, EMBED);

    // 1) h = LN1(x) -> bf16 hi/lo + f32
    ln_kernel<<<ROWS, 256>>>(x, ln1_g, ln1_b, h32, h_hi, h_lo);

    // 2) qkv = h @ w_qkv (bf16 3-MMA), Q cols pre-scaled 1/8
    gemm_mma<1,true><<<dim3(QKVW/128, ROWS/128), 256, SMG>>>(
        h_hi, h_lo, EMBED, wqkvT_hi, wqkvT_lo, EMBED,
        nullptr, qkv_hi, qkv_lo, QKVW, nullptr, nullptr, nullptr, EMBED);

    // 3) fused flash attention
    flash_attn<<<dim3(SEQ/128, BH), 256, SMF>>>(qkv_hi, qkv_lo, attn_hi, attn_lo);

    // 4) x2 = x + h + attn @ w_out + b_out (bf16 3-MMA)
    gemm_mma<2,false><<<dim3(EMBED/128, ROWS/128), 256, SMG>>>(
        attn_hi, attn_lo, EMBED, woutT_hi, woutT_lo, EMBED,
        x2, nullptr, nullptr, EMBED, b_out, x, h32, EMBED);

    // 5) h2 = LN2(x2) -> fp16 hi/lo
    ln16<<<ROWS, 256>>>(x2, ln2_g, ln2_b, h2_hi, h2_lo);

    // 6) mid = gelu(h2 @ w1 + b1)  (fp16, 2-MMA: A split, B single) -> fp16
    gemm_h<2,3><<<dim3(MLPD/128, ROWS/128), 256, SMH3>>>(
        h2_hi, h2_lo, EMBED, w1T16, EMBED,
        nullptr, mid16, MLPD, b1, nullptr, EMBED);

    // 7) out = x2 + mid @ w2 + b2  (fp16, 1-MMA)
    gemm_h<1,4><<<dim3(EMBED/128, ROWS/128), 256, SMH2>>>(
        mid16, nullptr, MLPD, w2T16, MLPD,
        out, nullptr, EMBED, b2, x2, MLPD);
}

// round 11
// speedup vs baseline: 7.3053x; 1.6190x over previous
#include <cuda_runtime.h>
#include <cuda_fp16.h>
#include <math.h>
#include <stdint.h>

#define EMBED 768
#define HEADS 12
#define HD    64
#define MLPD  3072
#define BATCH 4
#define SEQ   1024
#define ROWS  (BATCH*SEQ)
#define QKVW  (3*EMBED)
#define BH    (BATCH*HEADS)

// ------------------------- scratch ------------------------------------------
__device__ float  g_h32 [ROWS*EMBED];
__device__ __half g_h16 [ROWS*EMBED];
__device__ __half g_wqkvT16[QKVW*EMBED];
__device__ __half g_woutT16[EMBED*EMBED];
__device__ __half g_w1T16[MLPD*EMBED];
__device__ __half g_w2T16[EMBED*MLPD];
__device__ __half g_qkv16[ROWS*QKVW];
__device__ __half g_attn16[ROWS*EMBED];
__device__ float  g_x2[ROWS*EMBED];
__device__ __half g_h2_16[ROWS*EMBED];
__device__ __half g_mid16[ROWS*MLPD];

// ------------------------- helpers ------------------------------------------
__device__ __forceinline__ uint32_t smem_u32(const void* p){
    uint32_t a;
    asm("{ .reg .u64 t; cvta.to.shared.u64 t, %1; cvt.u32.u64 %0, t; }" : "=r"(a) : "l"(p));
    return a;
}
__device__ __forceinline__ void cp16(uint32_t dst, const void* src){
    asm volatile("cp.async.cg.shared.global [%0], [%1], 16;" :: "r"(dst), "l"(src));
}
__device__ __forceinline__ void ldsm4(uint32_t* r, uint32_t a){
    asm volatile("ldmatrix.sync.aligned.m8n8.x4.shared.b16 {%0,%1,%2,%3}, [%4];"
        : "=r"(r[0]),"=r"(r[1]),"=r"(r[2]),"=r"(r[3]) : "r"(a));
}
__device__ __forceinline__ void ldsm4t(uint32_t* r, uint32_t a){
    asm volatile("ldmatrix.sync.aligned.m8n8.x4.trans.shared.b16 {%0,%1,%2,%3}, [%4];"
        : "=r"(r[0]),"=r"(r[1]),"=r"(r[2]),"=r"(r[3]) : "r"(a));
}
__device__ __forceinline__ void ldsm2(uint32_t* r, uint32_t a){
    asm volatile("ldmatrix.sync.aligned.m8n8.x2.shared.b16 {%0,%1}, [%2];"
        : "=r"(r[0]),"=r"(r[1]) : "r"(a));
}
__device__ __forceinline__ void mma16816h(float* c, const uint32_t* a, const uint32_t* b){
    asm volatile("mma.sync.aligned.m16n8k16.row.col.f32.f16.f16.f32 "
        "{%0,%1,%2,%3}, {%4,%5,%6,%7}, {%8,%9}, {%0,%1,%2,%3};"
        : "+f"(c[0]),"+f"(c[1]),"+f"(c[2]),"+f"(c[3])
        : "r"(a[0]),"r"(a[1]),"r"(a[2]),"r"(a[3]), "r"(b[0]),"r"(b[1]));
}
__device__ __forceinline__ uint32_t pack_h2(__half a, __half b){
    return (uint32_t)__half_as_ushort(a) | ((uint32_t)__half_as_ushort(b) << 16);
}
__device__ __forceinline__ uint32_t pack_f2h(float x, float y){
    return pack_h2(__float2half(x), __float2half(y));
}

// ------------------------- weight transpose (fp16) --------------------------
__global__ void tconv16(const float* __restrict__ W, __half* __restrict__ T, int K, int N)
{
    __shared__ float s[32][33];
    const int n0 = blockIdx.x * 32, k0 = blockIdx.y * 32;
    const int tx = threadIdx.x, ty = threadIdx.y;
    #pragma unroll
    for (int i = 0; i < 4; i++)
        s[ty + i*8][tx] = W[(size_t)(k0 + ty + i*8) * N + n0 + tx];
    __syncthreads();
    #pragma unroll
    for (int i = 0; i < 4; i++) {
        const int n = ty + i*8;
        T[(size_t)(n0 + n) * K + k0 + tx] = __float2half(s[tx][n]);
    }
}

// ------------------------- LayerNorm -> fp16 (+opt f32) ---------------------
__global__ __launch_bounds__(256) void ln_h(const float* __restrict__ x,
                                            const float* __restrict__ g,
                                            const float* __restrict__ b,
                                            float* __restrict__ out32,
                                            __half* __restrict__ o16)
{
    const int row = blockIdx.x;
    const int t = threadIdx.x;
    const float* xr = x + (size_t)row * EMBED;
    float v0 = xr[t], v1 = xr[t+256], v2 = xr[t+512];
    float s = v0+v1+v2, sq = v0*v0+v1*v1+v2*v2;
    #pragma unroll
    for (int off = 16; off; off >>= 1) {
        s  += __shfl_xor_sync(0xffffffffu, s,  off);
        sq += __shfl_xor_sync(0xffffffffu, sq, off);
    }
    __shared__ float red[16];
    const int w = t >> 5;
    if ((t & 31) == 0) { red[w] = s; red[8+w] = sq; }
    __syncthreads();
    float tot = 0.f, totq = 0.f;
    #pragma unroll
    for (int i = 0; i < 8; i++) { tot += red[i]; totq += red[8+i]; }
    const float mu = tot * (1.f/768.f);
    const float var = totq * (1.f/768.f) - mu*mu;
    const float rstd = rsqrtf(fmaxf(var, 0.f) + 1e-5f);
    const size_t o = (size_t)row * EMBED;
    #pragma unroll
    for (int i = 0; i < 3; i++) {
        const int c = t + i*256;
        const float v = (i==0?v0:(i==1?v1:v2));
        const float y = (v - mu) * rstd * g[c] + b[c];
        if (out32) out32[o + c] = y;
        o16[o + c] = __float2half(y);
    }
}

// ------------------------- fp16 single-plane GEMM (1 MMA/k16) ---------------
// EPI 0: qkv out fp16 (cols<768 scaled 0.125)  1: fp16 gelu(+bias)
// EPI 2: f32 +bias+add1+add2                   3: f32 +bias+add1
template<int EPI>
__global__ void __launch_bounds__(256, 2) gemm_h16(
    const __half* __restrict__ A, int lda,
    const __half* __restrict__ B, int ldb,
    float* __restrict__ C, __half* __restrict__ Ch, int ldc,
    const float* __restrict__ bias, const float* __restrict__ add1, const float* __restrict__ add2,
    int K)
{
    constexpr int RS  = 80;
    constexpr int SP  = 128 * RS;   // 10240 per operand
    constexpr int BUF = 2 * SP;

    extern __shared__ char sm[];
    const uint32_t smb = smem_u32(sm);
    const int tid  = threadIdx.x;
    const int wid  = tid >> 5, lane = tid & 31;
    const int warp_m = wid & 1, warp_n = wid >> 1;
    const int rowBase = blockIdx.y * 128;
    const int colBase = blockIdx.x * 128;

    float acc[4][4][4];
    #pragma unroll
    for (int mt = 0; mt < 4; mt++)
        #pragma unroll
        for (int nt = 0; nt < 4; nt++)
            #pragma unroll
            for (int i = 0; i < 4; i++) acc[mt][nt][i] = 0.f;

    auto load_chunk = [&](int c) {
        const uint32_t st = smb + (c & 1)*BUF;
        const int k0 = c * 32;
        #pragma unroll
        for (int i = 0; i < 4; i++) {
            const int t = tid + i*256;
            const int pl = t >> 9, rem = t & 511, rr = rem >> 2, cg = rem & 3;
            const __half* src = pl ? B + (size_t)(colBase + rr) * ldb + k0 + cg*8
                                   : A + (size_t)(rowBase + rr) * lda + k0 + cg*8;
            cp16(st + pl*SP + rr*RS + cg*16, src);
        }
        asm volatile("cp.async.commit_group;");
    };

    load_chunk(0);
    const int NC = K / 32;
    for (int c = 0; c < NC; ++c) {
        asm volatile("cp.async.wait_group 0;" ::: "memory");
        __syncthreads();
        if (c + 1 < NC) load_chunk(c + 1);

        const uint32_t st = smb + (c & 1)*BUF;
        #pragma unroll
        for (int ks = 0; ks < 2; ks++) {
            uint32_t bf[4][2];
            #pragma unroll
            for (int nt = 0; nt < 4; nt++) {
                const int row = warp_n*32 + nt*8 + (lane & 7);
                ldsm2(bf[nt], st + SP + row*RS + ks*32 + ((lane >> 3) & 1)*16);
            }
            #pragma unroll
            for (int mt = 0; mt < 4; mt++) {
                const int row = warp_m*64 + mt*16 + (lane & 15);
                uint32_t af[4];
                ldsm4(af, st + row*RS + ks*32 + (lane >> 4)*16);
                #pragma unroll
                for (int nt = 0; nt < 4; nt++)
                    mma16816h(acc[mt][nt], af, bf[nt]);
            }
        }
    }

    #pragma unroll
    for (int mt = 0; mt < 4; mt++) {
        #pragma unroll
        for (int nt = 0; nt < 4; nt++) {
            const int gr0 = rowBase + warp_m*64 + mt*16 + (lane >> 2);
            const int gc  = colBase + warp_n*32 + nt*8 + (lane & 3)*2;
            #pragma unroll
            for (int half = 0; half < 2; half++) {
                const int gr = gr0 + half*8;
                const size_t idx = (size_t)gr * ldc + gc;
                float v0 = acc[mt][nt][half*2 + 0];
                float v1 = acc[mt][nt][half*2 + 1];
                if (EPI == 0) {
                    if (gc < EMBED) { v0 *= 0.125f; v1 *= 0.125f; }
                    *(uint32_t*)(Ch + idx) = pack_f2h(v0, v1);
                } else if (EPI == 1) {
                    v0 += bias[gc+0];
                    v1 += bias[gc+1];
                    v0 = 0.5f * v0 * (1.f + erff(v0 * 0.70710678118654752f));
                    v1 = 0.5f * v1 * (1.f + erff(v1 * 0.70710678118654752f));
                    *(uint32_t*)(Ch + idx) = pack_f2h(v0, v1);
                } else if (EPI == 2) {
                    v0 += bias[gc+0] + add1[idx+0] + add2[idx+0];
                    v1 += bias[gc+1] + add1[idx+1] + add2[idx+1];
                    *(float2*)(C + idx) = make_float2(v0, v1);
                } else {
                    v0 += bias[gc+0] + add1[idx+0];
                    v1 += bias[gc+1] + add1[idx+1];
                    *(float2*)(C + idx) = make_float2(v0, v1);
                }
            }
        }
    }
}

// ------------------------- fused flash attention (fp16 single) --------------
// grid (SEQ/128, BH), 256 thr. KV tiles 64 keys, double-buffered.
// 1 MMA for QK, 1 MMA-pair for PV. SMEM: Q 18432 + 2x(K 9216 + V 9216) = 55296.
__global__ void __launch_bounds__(256) flash_attn(
    const __half* __restrict__ qkv, __half* __restrict__ O)
{
    extern __shared__ char sm[];
    const uint32_t smb = smem_u32(sm);
    const int tid = threadIdx.x, lane = tid & 31, wid = tid >> 5;
    const int qt = blockIdx.x;
    const int b  = blockIdx.y / HEADS, h = blockIdx.y % HEADS;
    const size_t gbase = (size_t)b * SEQ * QKVW;
    const int hoff = h * HD;

    // Q: 128 rows x 8 16B-groups
    #pragma unroll
    for (int i = 0; i < 4; i++) {
        const int t = tid + i*256;
        const int r = t >> 3, cg = t & 7;
        cp16(smb + (uint32_t)(r*144 + cg*16),
             qkv + gbase + (size_t)(qt*128 + r)*QKVW + hoff + cg*8);
    }
    auto load_kv = [&](int j) {
        const uint32_t dst = smb + 18432 + (j & 1)*18432;
        #pragma unroll
        for (int i = 0; i < 4; i++) {
            const int t = tid + i*256;
            const int pl = t >> 9, rem = t & 511, r = rem >> 3, cg = rem & 7;
            cp16(dst + (uint32_t)(pl*9216 + r*144 + cg*16),
                 qkv + gbase + (size_t)(j*64 + r)*QKVW + EMBED + pl*EMBED + hoff + cg*8);
        }
        asm volatile("cp.async.commit_group;");
    };
    load_kv(0);   // commits Q + KV0

    const int warprow = wid * 16;
    float m0 = -1e30f, m1 = -1e30f, l0 = 0.f, l1 = 0.f;
    float o[8][4];
    #pragma unroll
    for (int nt = 0; nt < 8; nt++)
        #pragma unroll
        for (int i = 0; i < 4; i++) o[nt][i] = 0.f;

    for (int j = 0; j < 16; j++) {
        asm volatile("cp.async.wait_group 0;" ::: "memory");
        __syncthreads();
        if (j < 15) load_kv(j + 1);
        const uint32_t st = smb + 18432 + (j & 1)*18432;

        // ---- S = Q K^T (Q pre-scaled) ------------------------------------
        float s[8][4];
        #pragma unroll
        for (int nt = 0; nt < 8; nt++)
            #pragma unroll
            for (int i = 0; i < 4; i++) s[nt][i] = 0.f;
        #pragma unroll
        for (int ks = 0; ks < 4; ks++) {
            uint32_t qf[4];
            ldsm4(qf, smb + (uint32_t)((warprow + (lane & 15))*144 + ks*32 + (lane >> 4)*16));
            #pragma unroll
            for (int nt = 0; nt < 8; nt++) {
                uint32_t kf[2];
                ldsm2(kf, st + (uint32_t)((nt*8 + (lane & 7))*144 + ks*32 + ((lane >> 3) & 1)*16));
                mma16816h(s[nt], qf, kf);
            }
        }

        // ---- online softmax ----------------------------------------------
        float mt0 = s[0][0], mt1 = s[0][2];
        #pragma unroll
        for (int nt = 0; nt < 8; nt++) {
            mt0 = fmaxf(mt0, fmaxf(s[nt][0], s[nt][1]));
            mt1 = fmaxf(mt1, fmaxf(s[nt][2], s[nt][3]));
        }
        mt0 = fmaxf(mt0, __shfl_xor_sync(0xffffffffu, mt0, 1));
        mt0 = fmaxf(mt0, __shfl_xor_sync(0xffffffffu, mt0, 2));
        mt1 = fmaxf(mt1, __shfl_xor_sync(0xffffffffu, mt1, 1));
        mt1 = fmaxf(mt1, __shfl_xor_sync(0xffffffffu, mt1, 2));
        const float mn0 = fmaxf(m0, mt0), mn1 = fmaxf(m1, mt1);
        const float a0 = __expf(m0 - mn0), a1 = __expf(m1 - mn1);
        float rs0 = 0.f, rs1 = 0.f;
        #pragma unroll
        for (int nt = 0; nt < 8; nt++) {
            s[nt][0] = __expf(s[nt][0] - mn0); rs0 += s[nt][0];
            s[nt][1] = __expf(s[nt][1] - mn0); rs0 += s[nt][1];
            s[nt][2] = __expf(s[nt][2] - mn1); rs1 += s[nt][2];
            s[nt][3] = __expf(s[nt][3] - mn1); rs1 += s[nt][3];
        }
        rs0 += __shfl_xor_sync(0xffffffffu, rs0, 1);
        rs0 += __shfl_xor_sync(0xffffffffu, rs0, 2);
        rs1 += __shfl_xor_sync(0xffffffffu, rs1, 1);
        rs1 += __shfl_xor_sync(0xffffffffu, rs1, 2);
        l0 = l0 * a0 + rs0;  l1 = l1 * a1 + rs1;
        m0 = mn0;  m1 = mn1;
        #pragma unroll
        for (int nt = 0; nt < 8; nt++) {
            o[nt][0] *= a0; o[nt][1] *= a0;
            o[nt][2] *= a1; o[nt][3] *= a1;
        }

        // ---- P fragments (single fp16) -----------------------------------
        uint32_t ph[4][4];
        #pragma unroll
        for (int ks = 0; ks < 4; ks++) {
            ph[ks][0] = pack_f2h(s[2*ks][0],   s[2*ks][1]);
            ph[ks][1] = pack_f2h(s[2*ks][2],   s[2*ks][3]);
            ph[ks][2] = pack_f2h(s[2*ks+1][0], s[2*ks+1][1]);
            ph[ks][3] = pack_f2h(s[2*ks+1][2], s[2*ks+1][3]);
        }

        // ---- O += P V ----------------------------------------------------
        #pragma unroll
        for (int ks = 0; ks < 4; ks++) {
            #pragma unroll
            for (int ntp = 0; ntp < 4; ntp++) {
                uint32_t vf[4];
                const uint32_t va = st + 9216
                    + (uint32_t)((ks*16 + ((lane >> 3) & 1)*8 + (lane & 7))*144
                                 + ntp*32 + (lane >> 4)*16);
                ldsm4t(vf, va);
                mma16816h(o[2*ntp],   ph[ks], &vf[0]);
                mma16816h(o[2*ntp+1], ph[ks], &vf[2]);
            }
        }
    }

    // ---- finalize + write fp16 ----------------------------------------
    const float rl0 = 1.f / l0, rl1 = 1.f / l1;
    const int gr = b*SEQ + qt*128 + warprow + (lane >> 2);
    #pragma unroll
    for (int nt = 0; nt < 8; nt++) {
        const int gc = hoff + nt*8 + (lane & 3)*2;
        const size_t i0 = (size_t)gr * EMBED + gc;
        const size_t i1 = i0 + (size_t)8 * EMBED;
        *(uint32_t*)(O + i0) = pack_f2h(o[nt][0]*rl0, o[nt][1]*rl0);
        *(uint32_t*)(O + i1) = pack_f2h(o[nt][2]*rl1, o[nt][3]*rl1);
    }
}

// ------------------------- host ---------------------------------------------
extern "C" void kernel_launch(void* const* d_in, const int* in_sizes, int n_in,
                              void* d_out, int out_size)
{
    const float* x     = (const float*)d_in[0];
    const float* ln1_g = (const float*)d_in[1];
    const float* ln1_b = (const float*)d_in[2];
    const float* w_qkv = (const float*)d_in[3];
    const float* w_out = (const float*)d_in[4];
    const float* b_out = (const float*)d_in[5];
    const float* ln2_g = (const float*)d_in[6];
    const float* ln2_b = (const float*)d_in[7];
    const float* w1    = (const float*)d_in[8];
    const float* b1    = (const float*)d_in[9];
    const float* w2    = (const float*)d_in[10];
    const float* b2    = (const float*)d_in[11];
    float* out = (float*)d_out;

    float *h32, *x2;
    __half *h16,*wqkvT16,*woutT16,*w1T16,*w2T16,*qkv16,*attn16,*h2_16,*mid16;
    cudaGetSymbolAddress((void**)&h32, g_h32);
    cudaGetSymbolAddress((void**)&h16, g_h16);
    cudaGetSymbolAddress((void**)&wqkvT16, g_wqkvT16);
    cudaGetSymbolAddress((void**)&woutT16, g_woutT16);
    cudaGetSymbolAddress((void**)&w1T16, g_w1T16);
    cudaGetSymbolAddress((void**)&w2T16, g_w2T16);
    cudaGetSymbolAddress((void**)&qkv16, g_qkv16);
    cudaGetSymbolAddress((void**)&attn16, g_attn16);
    cudaGetSymbolAddress((void**)&x2, g_x2);
    cudaGetSymbolAddress((void**)&h2_16, g_h2_16);
    cudaGetSymbolAddress((void**)&mid16, g_mid16);

    const int SMH = 2 * 2 * 128 * 80;   // 40960
    const int SMF = 55296;
    cudaFuncSetAttribute(gemm_h16<0>, cudaFuncAttributeMaxDynamicSharedMemorySize, SMH);
    cudaFuncSetAttribute(gemm_h16<1>, cudaFuncAttributeMaxDynamicSharedMemorySize, SMH);
    cudaFuncSetAttribute(gemm_h16<2>, cudaFuncAttributeMaxDynamicSharedMemorySize, SMH);
    cudaFuncSetAttribute(gemm_h16<3>, cudaFuncAttributeMaxDynamicSharedMemorySize, SMH);
    cudaFuncSetAttribute(flash_attn,  cudaFuncAttributeMaxDynamicSharedMemorySize, SMF);

    // weight prep (all single fp16, transposed to [N][K])
    tconv16<<<dim3(QKVW/32, EMBED/32), dim3(32,8)>>>(w_qkv, wqkvT16, EMBED, QKVW);
    tconv16<<<dim3(EMBED/32, EMBED/32), dim3(32,8)>>>(w_out, woutT16, EMBED, EMBED);
    tconv16<<<dim3(MLPD/32, EMBED/32), dim3(32,8)>>>(w1, w1T16, EMBED, MLPD);
    tconv16<<<dim3(EMBED/32, MLPD/32), dim3(32,8)>>>(w2, w2T16, MLPD, EMBED);

    // 1) h = LN1(x) -> fp16 + f32
    ln_h<<<ROWS, 256>>>(x, ln1_g, ln1_b, h32, h16);

    // 2) qkv = h @ w_qkv (1 MMA), Q cols pre-scaled 1/8
    gemm_h16<0><<<dim3(QKVW/128, ROWS/128), 256, SMH>>>(
        h16, EMBED, wqkvT16, EMBED,
        nullptr, qkv16, QKVW, nullptr, nullptr, nullptr, EMBED);

    // 3) fused flash attention (fp16)
    flash_attn<<<dim3(SEQ/128, BH), 256, SMF>>>(qkv16, attn16);

    // 4) x2 = x + h + attn @ w_out + b_out (1 MMA)
    gemm_h16<2><<<dim3(EMBED/128, ROWS/128), 256, SMH>>>(
        attn16, EMBED, woutT16, EMBED,
        x2, nullptr, EMBED, b_out, x, h32, EMBED);

    // 5) h2 = LN2(x2) -> fp16
    ln_h<<<ROWS, 256>>>(x2, ln2_g, ln2_b, nullptr, h2_16);

    // 6) mid = gelu(h2 @ w1 + b1) (1 MMA) -> fp16
    gemm_h16<1><<<dim3(MLPD/128, ROWS/128), 256, SMH>>>(
        h2_16, EMBED, w1T16, EMBED,
        nullptr, mid16, MLPD, b1, nullptr, nullptr, EMBED);

    // 7) out = x2 + mid @ w2 + b2 (1 MMA)
    gemm_h16<3><<<dim3(EMBED/128, ROWS/128), 256, SMH>>>(
        mid16, MLPD, w2T16, MLPD,
        out, nullptr, EMBED, b2, x2, nullptr, MLPD);
}